// round 13
// baseline (speedup 1.0000x reference)
#include <cuda_runtime.h>
#include <cuda_bf16.h>
#include <cstdint>

// ---------------------------------------------------------------------------
// Problem constants
// ---------------------------------------------------------------------------
#define BATCH   512
#define MAXLEN  128
#define D_DRUG  256
#define D_CELL  1024
#define NHEAD   16
#define HDIM    64
#define EMB     1024   // NHEAD*HDIM

// ---------------------------------------------------------------------------
// Scratch (device globals)
// ---------------------------------------------------------------------------
__device__ float g_qk  [BATCH * NHEAD * D_DRUG];
__device__ float g_part[4 * BATCH * EMB];          // split-K partials
__device__ int   g_seg [BATCH + 1];
__device__ int   g_cnt [4 * 128];                  // per-GEMM tile semaphores

__device__ __nv_bfloat16 g_a0h[BATCH * EMB],   g_a0l[BATCH * EMB];
__device__ __nv_bfloat16 g_a1h[BATCH * EMB],   g_a1l[BATCH * EMB];
__device__ __nv_bfloat16 g_xah[BATCH * NHEAD * D_DRUG], g_xal[BATCH * NHEAD * D_DRUG];
__device__ __nv_bfloat16 g_wch[EMB * D_CELL],  g_wcl[EMB * D_CELL];
__device__ __nv_bfloat16 g_wqh[EMB * EMB],     g_wql[EMB * EMB];
__device__ __nv_bfloat16 g_woh[EMB * EMB],     g_wol[EMB * EMB];
__device__ __nv_bfloat16 g_wvh[EMB * D_DRUG],  g_wvl[EMB * D_DRUG];
__device__ __nv_bfloat16 g_wkth[NHEAD * D_DRUG * HDIM], g_wktl[NHEAD * D_DRUG * HDIM];

// ---------------------------------------------------------------------------
// Helpers
// ---------------------------------------------------------------------------
union F2U { float2 f; unsigned long long u; };
__device__ __forceinline__ void fma2(F2U &c, F2U a, F2U b) {
    asm("fma.rn.f32x2 %0, %1, %2, %0;" : "+l"(c.u) : "l"(a.u), "l"(b.u));
}

__device__ __forceinline__ uint32_t smem_u32(const void* p) {
    uint32_t a;
    asm("{ .reg .u64 t; cvta.to.shared.u64 t, %1; cvt.u32.u64 %0, t; }" : "=r"(a) : "l"(p));
    return a;
}

__device__ __forceinline__ void ldsm4(uint32_t &r0, uint32_t &r1, uint32_t &r2, uint32_t &r3,
                                      uint32_t a) {
    asm volatile("ldmatrix.sync.aligned.m8n8.x4.shared.b16 {%0,%1,%2,%3}, [%4];"
        : "=r"(r0), "=r"(r1), "=r"(r2), "=r"(r3) : "r"(a));
}

__device__ __forceinline__ void mma_bf16(float c[4], const uint32_t a[4],
                                         uint32_t b0, uint32_t b1) {
    asm volatile("mma.sync.aligned.m16n8k16.row.col.f32.bf16.bf16.f32 "
        "{%0,%1,%2,%3}, {%4,%5,%6,%7}, {%8,%9}, {%0,%1,%2,%3};"
        : "+f"(c[0]), "+f"(c[1]), "+f"(c[2]), "+f"(c[3])
        : "r"(a[0]), "r"(a[1]), "r"(a[2]), "r"(a[3]), "r"(b0), "r"(b1));
}

__device__ __forceinline__ uint32_t pack_bf16(float a, float b) {
    return (uint32_t)__bfloat16_as_ushort(__float2bfloat16(a))
         | ((uint32_t)__bfloat16_as_ushort(__float2bfloat16(b)) << 16);
}

#define CPA16(sm, gp) asm volatile("cp.async.cg.shared.global [%0], [%1], 16;" :: "r"(sm), "l"(gp))
#define CP_COMMIT()   asm volatile("cp.async.commit_group;" ::: "memory")
#define CP_WAIT0()    asm volatile("cp.async.wait_group 0;" ::: "memory")
#define CP_WAIT1()    asm volatile("cp.async.wait_group 1;" ::: "memory")

// ---------------------------------------------------------------------------
// Fused prep kernel: splits + WkT + seg + copy + counter reset
// ---------------------------------------------------------------------------
__device__ __forceinline__ void split4(const float4* s, uint2* hi, uint2* lo, int i)
{
    float4 v = s[i];
    __nv_bfloat16 h0 = __float2bfloat16(v.x), h1 = __float2bfloat16(v.y);
    __nv_bfloat16 h2 = __float2bfloat16(v.z), h3 = __float2bfloat16(v.w);
    uint2 H, L;
    H.x = (uint32_t)__bfloat16_as_ushort(h0) | ((uint32_t)__bfloat16_as_ushort(h1) << 16);
    H.y = (uint32_t)__bfloat16_as_ushort(h2) | ((uint32_t)__bfloat16_as_ushort(h3) << 16);
    L.x = pack_bf16(v.x - __bfloat162float(h0), v.y - __bfloat162float(h1));
    L.y = pack_bf16(v.z - __bfloat162float(h2), v.w - __bfloat162float(h3));
    hi[i] = H; lo[i] = L;
}

__global__ __launch_bounds__(256)
void prep_kernel(const float4* Wc, const float4* Wq, const float4* Wo,
                 const float4* Wv, const float4* cell, const float* Wk,
                 const void* guide, int n,
                 uint2* wch, uint2* wcl, uint2* wqh, uint2* wql,
                 uint2* woh, uint2* wol, uint2* wvh, uint2* wvl,
                 uint2* ah, uint2* al,
                 __nv_bfloat16* wkth, __nv_bfloat16* wktl,
                 int* seg, float4* outp, int* cnt)
{
    __shared__ float tile[32][33];
    int blk = blockIdx.x, t = threadIdx.x;

    if (blk < 3840) {
        int i = blk * 256 + t;
        if      (i < 262144)  split4(Wc, wch, wcl, i);
        else if (i < 524288)  split4(Wq, wqh, wql, i - 262144);
        else if (i < 786432)  split4(Wo, woh, wol, i - 524288);
        else if (i < 851968)  split4(Wv, wvh, wvl, i - 786432);
        else if (i < 983040)  split4(cell, ah, al, i - 851968);
    } else if (blk < 4096) {
        int b2 = blk - 3840;
        int nt = b2 & 7, dt = (b2 >> 3) & 1, h = b2 >> 4;
        int tx = t & 31, ty = t >> 5;
#pragma unroll
        for (int r = ty; r < 32; r += 8)
            tile[r][tx] = Wk[(long long)(h * 64 + dt * 32 + r) * D_DRUG + nt * 32 + tx];
        __syncthreads();
#pragma unroll
        for (int r = ty; r < 32; r += 8) {
            float v = tile[tx][r];
            __nv_bfloat16 hh = __float2bfloat16(v);
            long long o = (long long)h * (D_DRUG * HDIM)
                        + (long long)(nt * 32 + r) * HDIM + dt * 32 + tx;
            wkth[o] = hh;
            wktl[o] = __float2bfloat16(v - __bfloat162float(hh));
        }
    } else if (blk < 4099) {
        int g = (blk - 4096) * 256 + t;
        if (g <= BATCH) {
            const unsigned long long* g64 = (const unsigned long long*)guide;
            const int*                g32 = (const int*)guide;
            bool is64 = (g64[(n >> 1) - 1] <= 511ull);
            int lo2 = 0, hi2 = n;
            while (lo2 < hi2) {
                int mid = (lo2 + hi2) >> 1;
                long long v = is64 ? (long long)g64[mid] : (long long)g32[mid];
                if (v < (long long)g) lo2 = mid + 1; else hi2 = mid;
            }
            seg[g] = lo2;
        }
    } else if (blk < 4611) {
        int i = (blk - 4099) * 256 + t;
        if (i < BATCH * (D_CELL / 4)) {
            int b = i >> 8, j = i & 255;
            outp[b * ((EMB + D_CELL) / 4) + (EMB / 4) + j] = cell[i];
        }
    } else {
        // reset split-K semaphores (4 GEMMs x 128 tiles)
        cnt[t] = 0;
        cnt[t + 256] = 0;
    }
}

// ---------------------------------------------------------------------------
// bf16x3 MMA GEMM (R9 config: 256 thr, 64x64 CTA, 2x4 warps of 32x16,
// 2-stage cp.async, static 40KB) with FUSED split-K reduction:
// each CTA writes its fp32 partial + threadfence + semaphore; the last
// CTA per output tile re-reads the other slices and sums in fixed slice
// order (own slice from registers) -> bit-deterministic.
// MODE 0: final bf16 hi/lo alpha*(acc+bias).  MODE 1: final fp32.
// ---------------------------------------------------------------------------
template <int MODE>
__global__ __launch_bounds__(256)
void mma_gemm3x(const __nv_bfloat16* __restrict__ Ah, const __nv_bfloat16* __restrict__ Al,
                int lda, long long sAz,
                const __nv_bfloat16* __restrict__ Wh, const __nv_bfloat16* __restrict__ Wl,
                int ldw, long long sWz,
                const float* __restrict__ bias, long long sbz,
                float* __restrict__ Cf,
                __nv_bfloat16* __restrict__ Ch, __nv_bfloat16* __restrict__ Cl,
                int ldc, long long sCz,
                float* __restrict__ part, int ldp, long long pstr, long long sPz,
                int* __restrict__ cnt,
                float alpha, int Kslice, int nks)
{
    __shared__ __align__(16) char smraw[40960];
    __shared__ int lastFlag;

    int zb = blockIdx.z / nks, zk = blockIdx.z % nks;
    const __nv_bfloat16* Ah_ = Ah + (long long)zb * sAz + (long long)zk * Kslice;
    const __nv_bfloat16* Al_ = Al + (long long)zb * sAz + (long long)zk * Kslice;
    const __nv_bfloat16* Wh_ = Wh + (long long)zb * sWz + (long long)zk * Kslice;
    const __nv_bfloat16* Wl_ = Wl + (long long)zb * sWz + (long long)zk * Kslice;
    const float* bp = bias ? bias + (long long)zb * sbz : nullptr;

    int tid = threadIdx.x, lane = tid & 31, warp = tid >> 5;
    int wm = warp >> 2, wn = warp & 3;            // 2 x 4 warps, 32x16 tiles
    int m0 = blockIdx.y * 64, n0 = blockIdx.x * 64;

    int lr = tid >> 2;
    int lq = (tid & 3) * 8;
    int lo = lr * 80 + (tid & 3) * 16;

    const __nv_bfloat16* pAh = Ah_ + (long long)(m0 + lr) * lda + lq;
    const __nv_bfloat16* pAl = Al_ + (long long)(m0 + lr) * lda + lq;
    const __nv_bfloat16* pWh = Wh_ + (long long)(n0 + lr) * ldw + lq;
    const __nv_bfloat16* pWl = Wl_ + (long long)(n0 + lr) * ldw + lq;

    uint32_t smb = smem_u32(smraw);

    auto issue = [&](uint32_t so, int k0) {
        CPA16(smb + so + lo,          (const char*)(pAh + k0));
        CPA16(smb + so + 5120  + lo,  (const char*)(pAl + k0));
        CPA16(smb + so + 10240 + lo,  (const char*)(pWh + k0));
        CPA16(smb + so + 15360 + lo,  (const char*)(pWl + k0));
        CP_COMMIT();
    };

    float acc[2][2][4];
#pragma unroll
    for (int s = 0; s < 2; s++)
#pragma unroll
        for (int nb = 0; nb < 2; nb++)
#pragma unroll
            for (int i = 0; i < 4; i++) acc[s][nb][i] = 0.f;

    uint32_t aBase = smb + (uint32_t)((wm * 32 + (lane & 15)) * 80 + ((lane >> 4) & 1) * 16);
    uint32_t bBase = smb + 10240u +
        (uint32_t)((wn * 16 + ((lane >> 4) & 1) * 8 + (lane & 7)) * 80 + ((lane >> 3) & 1) * 16);

    int NT = Kslice / 32;
    issue(0, 0);
    if (NT > 1) issue(20480, 32);

    for (int t = 0; t < NT; t++) {
        if (t + 1 < NT) { CP_WAIT1(); } else { CP_WAIT0(); }
        __syncthreads();

        uint32_t bufo = (uint32_t)(t & 1) * 20480u;
#pragma unroll
        for (int kk = 0; kk < 2; kk++) {
            uint32_t ah[2][4], alr[2][4];
#pragma unroll
            for (int s = 0; s < 2; s++) {
                uint32_t ad = aBase + bufo + (uint32_t)(s * 1280 + kk * 32);
                ldsm4(ah[s][0], ah[s][1], ah[s][2], ah[s][3], ad);
                ldsm4(alr[s][0], alr[s][1], alr[s][2], alr[s][3], ad + 5120u);
            }
            uint32_t bh[2][2], blr[2][2];
            {
                uint32_t bd = bBase + bufo + (uint32_t)(kk * 32);
                ldsm4(bh[0][0], bh[0][1], bh[1][0], bh[1][1], bd);
                ldsm4(blr[0][0], blr[0][1], blr[1][0], blr[1][1], bd + 5120u);
            }
            mma_bf16(acc[0][0], ah[0],  bh[0][0],  bh[0][1]);
            mma_bf16(acc[0][1], ah[0],  bh[1][0],  bh[1][1]);
            mma_bf16(acc[1][0], ah[1],  bh[0][0],  bh[0][1]);
            mma_bf16(acc[1][1], ah[1],  bh[1][0],  bh[1][1]);

            mma_bf16(acc[0][0], ah[0],  blr[0][0], blr[0][1]);
            mma_bf16(acc[0][1], ah[0],  blr[1][0], blr[1][1]);
            mma_bf16(acc[1][0], ah[1],  blr[0][0], blr[0][1]);
            mma_bf16(acc[1][1], ah[1],  blr[1][0], blr[1][1]);

            mma_bf16(acc[0][0], alr[0], bh[0][0],  bh[0][1]);
            mma_bf16(acc[0][1], alr[0], bh[1][0],  bh[1][1]);
            mma_bf16(acc[1][0], alr[1], bh[0][0],  bh[0][1]);
            mma_bf16(acc[1][1], alr[1], bh[1][0],  bh[1][1]);
        }
        __syncthreads();
        if (t + 2 < NT) issue((uint32_t)(t & 1) * 20480u, (t + 2) * 32);
    }

    int erow = lane >> 2;
    int ecol = (lane & 3) * 2;

    if (nks > 1) {
        // write own partial slice
        long long po = (long long)zk * pstr + (long long)zb * sPz;
#pragma unroll
        for (int s = 0; s < 2; s++) {
            int r0 = m0 + wm * 32 + s * 16 + erow;
#pragma unroll
            for (int nb = 0; nb < 2; nb++) {
                int col = n0 + wn * 16 + nb * 8 + ecol;
                *(float2*)(part + po + (long long)r0 * ldp + col)
                    = make_float2(acc[s][nb][0], acc[s][nb][1]);
                *(float2*)(part + po + (long long)(r0 + 8) * ldp + col)
                    = make_float2(acc[s][nb][2], acc[s][nb][3]);
            }
        }
        __threadfence();
        int tile_id = (zb * gridDim.y + blockIdx.y) * gridDim.x + blockIdx.x;
        if (tid == 0) lastFlag = (atomicAdd(&cnt[tile_id], 1) == nks - 1);
        __syncthreads();
        if (!lastFlag) return;
        __threadfence();   // acquire other CTAs' partials
    }

    // final epilogue (reduce across slices in fixed index order)
    long long coff = (long long)zb * sCz;
#pragma unroll
    for (int s = 0; s < 2; s++) {
        int r0 = m0 + wm * 32 + s * 16 + erow;
#pragma unroll
        for (int nb = 0; nb < 2; nb++) {
            int col = n0 + wn * 16 + nb * 8 + ecol;
            float v00, v01, v10, v11;
            if (nks > 1) {
                v00 = v01 = v10 = v11 = 0.f;
                for (int k = 0; k < nks; k++) {
                    if (k == zk) {
                        v00 += acc[s][nb][0]; v01 += acc[s][nb][1];
                        v10 += acc[s][nb][2]; v11 += acc[s][nb][3];
                    } else {
                        long long pk = (long long)k * pstr + (long long)zb * sPz;
                        float2 a = *(const float2*)(part + pk + (long long)r0 * ldp + col);
                        float2 b = *(const float2*)(part + pk + (long long)(r0 + 8) * ldp + col);
                        v00 += a.x; v01 += a.y; v10 += b.x; v11 += b.y;
                    }
                }
            } else {
                v00 = acc[s][nb][0]; v01 = acc[s][nb][1];
                v10 = acc[s][nb][2]; v11 = acc[s][nb][3];
            }
            float b0 = bp ? bp[col] : 0.f;
            float b1 = bp ? bp[col + 1] : 0.f;
            v00 = alpha * (v00 + b0); v01 = alpha * (v01 + b1);
            v10 = alpha * (v10 + b0); v11 = alpha * (v11 + b1);
            if (MODE == 1) {
                *(float2*)(Cf + coff + (long long)r0 * ldc + col)       = make_float2(v00, v01);
                *(float2*)(Cf + coff + (long long)(r0 + 8) * ldc + col) = make_float2(v10, v11);
            } else {
                __nv_bfloat16 h00 = __float2bfloat16(v00), h01 = __float2bfloat16(v01);
                __nv_bfloat16 h10 = __float2bfloat16(v10), h11 = __float2bfloat16(v11);
                uint32_t ph0 = (uint32_t)__bfloat16_as_ushort(h00)
                             | ((uint32_t)__bfloat16_as_ushort(h01) << 16);
                uint32_t ph1 = (uint32_t)__bfloat16_as_ushort(h10)
                             | ((uint32_t)__bfloat16_as_ushort(h11) << 16);
                uint32_t pl0 = pack_bf16(v00 - __bfloat162float(h00), v01 - __bfloat162float(h01));
                uint32_t pl1 = pack_bf16(v10 - __bfloat162float(h10), v11 - __bfloat162float(h11));
                *(uint32_t*)(Ch + coff + (long long)r0 * ldc + col)       = ph0;
                *(uint32_t*)(Ch + coff + (long long)(r0 + 8) * ldc + col) = ph1;
                *(uint32_t*)(Cl + coff + (long long)r0 * ldc + col)       = pl0;
                *(uint32_t*)(Cl + coff + (long long)(r0 + 8) * ldc + col) = pl1;
            }
        }
    }
}

// ---------------------------------------------------------------------------
// Fused attention (R10/R11 version — online softmax, col-sliced xa)
// ---------------------------------------------------------------------------
__global__ __launch_bounds__(256)
void attn_kernel(const float* __restrict__ x,
                 const float* __restrict__ qk,
                 const int*   __restrict__ seg,
                 __nv_bfloat16* __restrict__ xah,
                 __nv_bfloat16* __restrict__ xal)
{
    __shared__ float qks[16 * 260];
    __shared__ float xs [16 * 260];
    __shared__ float sw [16 * 20];
    __shared__ float sscale[16];
    __shared__ float sD[16];

    int b = blockIdx.x;
    int t = threadIdx.x;
    int s0 = seg[b];
    int len = seg[b + 1] - s0;
    if (len > MAXLEN) len = MAXLEN;

    const float4* qk4 = (const float4*)(qk + (long long)b * (NHEAD * D_DRUG));
#pragma unroll
    for (int r = 0; r < 4; r++) {
        int idx = t + r * 256;
        int h = idx >> 6, jj = idx & 63;
        *(float4*)&qks[h * 260 + jj * 4] = qk4[idx];
    }
    __syncthreads();

    int h  = t >> 4;
    int mm = t & 15;
    int w2 = t >> 5, lane = t & 31;
    int hx = lane >> 1, cx = lane & 1;
    int j0x = w2 * 32 + cx * 16;

    float M = -3.0e38f, D = 0.f;
    F2U acc[8];
#pragma unroll
    for (int i = 0; i < 8; i++) acc[i].f = make_float2(0.f, 0.f);

    for (int m0 = 0; m0 < len; m0 += 16) {
        int nm = len - m0; if (nm > 16) nm = 16;
#pragma unroll
        for (int r = 0; r < 4; r++) {
            int idx = t + r * 256;
            int row = idx >> 6, jj = idx & 63;
            if (row < nm)
                *(float4*)&xs[row * 260 + jj * 4] =
                    *(const float4*)(x + (long long)(s0 + m0 + row) * D_DRUG + jj * 4);
        }
        __syncthreads();

        float myscore = -3.0e38f;
        if (mm < nm) {
            const float* qp = &qks[h * 260];
            const float* xp = &xs[mm * 260];
            F2U a0, a1;
            a0.f = make_float2(0.f, 0.f);
            a1.f = make_float2(0.f, 0.f);
#pragma unroll
            for (int j = 0; j < 256; j += 8) {
                float4 q0 = *(const float4*)(qp + j);
                float4 x0 = *(const float4*)(xp + j);
                float4 q1 = *(const float4*)(qp + j + 4);
                float4 x1 = *(const float4*)(xp + j + 4);
                F2U aa, bb;
                aa.f = make_float2(q0.x, q0.y); bb.f = make_float2(x0.x, x0.y); fma2(a0, aa, bb);
                aa.f = make_float2(q0.z, q0.w); bb.f = make_float2(x0.z, x0.w); fma2(a1, aa, bb);
                aa.f = make_float2(q1.x, q1.y); bb.f = make_float2(x1.x, x1.y); fma2(a0, aa, bb);
                aa.f = make_float2(q1.z, q1.w); bb.f = make_float2(x1.z, x1.w); fma2(a1, aa, bb);
            }
            myscore = a0.f.x + a0.f.y + a1.f.x + a1.f.y;
        }

        float tmax = myscore;
#pragma unroll
        for (int o = 1; o < 16; o <<= 1)
            tmax = fmaxf(tmax, __shfl_xor_sync(0xffffffffu, tmax, o));
        float newM = fmaxf(M, tmax);
        float scale = __expf(M - newM);
        float w = (mm < nm) ? __expf(myscore - newM) : 0.f;
        float ws = w;
#pragma unroll
        for (int o = 1; o < 16; o <<= 1)
            ws += __shfl_xor_sync(0xffffffffu, ws, o);
        D = D * scale + ws;
        M = newM;
        sw[h * 20 + mm] = w;
        if (mm == 0) sscale[h] = scale;
        __syncthreads();

        float sc2 = sscale[hx];
#pragma unroll
        for (int i = 0; i < 8; i++) { acc[i].f.x *= sc2; acc[i].f.y *= sc2; }
        const float* swr = &sw[hx * 20];
        for (int i = 0; i < nm; i++) {
            float a = swr[i];
            F2U ad; ad.f = make_float2(a, a);
            const float* xr = &xs[i * 260 + j0x];
#pragma unroll
            for (int r = 0; r < 4; r++) {
                float4 v = *(const float4*)(xr + r * 4);
                F2U b0, b1;
                b0.f = make_float2(v.x, v.y);
                b1.f = make_float2(v.z, v.w);
                fma2(acc[2 * r], ad, b0);
                fma2(acc[2 * r + 1], ad, b1);
            }
        }
        __syncthreads();
    }

    if (mm == 0) sD[h] = D;
    __syncthreads();

    float Df = sD[hx];
    float inv = (Df > 0.f) ? (1.0f / Df) : 0.f;
    long long base = (long long)b * (NHEAD * D_DRUG) + hx * D_DRUG + j0x;
#pragma unroll
    for (int i = 0; i < 8; i++) {
        float va = acc[i].f.x * inv, vb = acc[i].f.y * inv;
        __nv_bfloat16 ha = __float2bfloat16(va), hb = __float2bfloat16(vb);
        uint32_t ph = (uint32_t)__bfloat16_as_ushort(ha)
                    | ((uint32_t)__bfloat16_as_ushort(hb) << 16);
        uint32_t pl = pack_bf16(va - __bfloat162float(ha), vb - __bfloat162float(hb));
        *(uint32_t*)(xah + base + i * 2) = ph;
        *(uint32_t*)(xal + base + i * 2) = pl;
    }
}

// ---------------------------------------------------------------------------
// Launch (7 kernels: prep, G1, G2, qk, attn, vv, G3)
// ---------------------------------------------------------------------------
extern "C" void kernel_launch(void* const* d_in, const int* in_sizes, int n_in,
                              void* d_out, int out_size)
{
    const float* x_nodes = (const float*)d_in[0];
    const float* cell    = (const float*)d_in[1];
    const float* Wq      = (const float*)d_in[2];
    const float* bq      = (const float*)d_in[3];
    const float* Wk      = (const float*)d_in[4];
    /* bk cancels in softmax */
    const float* Wv      = (const float*)d_in[6];
    const float* bv      = (const float*)d_in[7];
    const float* Wo      = (const float*)d_in[8];
    const float* bo      = (const float*)d_in[9];
    const float* Wc      = (const float*)d_in[10];
    const float* bc      = (const float*)d_in[11];
    const void*  guide   = d_in[12];
    float*       out     = (float*)d_out;

    int N = in_sizes[12];

    float *qkp, *part; int *seg, *cnt;
    __nv_bfloat16 *a0h, *a0l, *a1h, *a1l, *xah, *xal;
    __nv_bfloat16 *wch, *wcl, *wqh, *wql, *woh, *wol, *wvh, *wvl, *wkth, *wktl;
    cudaGetSymbolAddress((void**)&qkp,  g_qk);
    cudaGetSymbolAddress((void**)&part, g_part);
    cudaGetSymbolAddress((void**)&seg,  g_seg);
    cudaGetSymbolAddress((void**)&cnt,  g_cnt);
    cudaGetSymbolAddress((void**)&a0h,  g_a0h);
    cudaGetSymbolAddress((void**)&a0l,  g_a0l);
    cudaGetSymbolAddress((void**)&a1h,  g_a1h);
    cudaGetSymbolAddress((void**)&a1l,  g_a1l);
    cudaGetSymbolAddress((void**)&xah,  g_xah);
    cudaGetSymbolAddress((void**)&xal,  g_xal);
    cudaGetSymbolAddress((void**)&wch,  g_wch);
    cudaGetSymbolAddress((void**)&wcl,  g_wcl);
    cudaGetSymbolAddress((void**)&wqh,  g_wqh);
    cudaGetSymbolAddress((void**)&wql,  g_wql);
    cudaGetSymbolAddress((void**)&woh,  g_woh);
    cudaGetSymbolAddress((void**)&wol,  g_wol);
    cudaGetSymbolAddress((void**)&wvh,  g_wvh);
    cudaGetSymbolAddress((void**)&wvl,  g_wvl);
    cudaGetSymbolAddress((void**)&wkth, g_wkth);
    cudaGetSymbolAddress((void**)&wktl, g_wktl);

    const long long PSTR = (long long)BATCH * EMB;

    // 1: fused prep (+ semaphore reset)
    prep_kernel<<<4612, 256>>>((const float4*)Wc, (const float4*)Wq, (const float4*)Wo,
                               (const float4*)Wv, (const float4*)cell, Wk, guide, N,
                               (uint2*)wch, (uint2*)wcl, (uint2*)wqh, (uint2*)wql,
                               (uint2*)woh, (uint2*)wol, (uint2*)wvh, (uint2*)wvl,
                               (uint2*)a0h, (uint2*)a0l, wkth, wktl, seg, (float4*)out, cnt);

    // 2: G1 cq = cell @ Wc^T + bc  (fused split-K4 -> a1 hi/lo)
    mma_gemm3x<0><<<dim3(16, 8, 4), 256>>>(
        a0h, a0l, D_CELL, 0, wch, wcl, D_CELL, 0, bc, 0,
        nullptr, a1h, a1l, EMB, 0,
        part, EMB, PSTR, 0, cnt + 0 * 128, 1.0f, 256, 4);

    // 3: G2 q = (cq @ Wq^T + bq)*0.125  (fused split-K4 -> a0 hi/lo)
    mma_gemm3x<0><<<dim3(16, 8, 4), 256>>>(
        a1h, a1l, EMB, 0, wqh, wql, EMB, 0, bq, 0,
        nullptr, a0h, a0l, EMB, 0,
        part, EMB, PSTR, 0, cnt + 1 * 128, 0.125f, 256, 4);

    // 4 (profiled slot): qk = q @ WkT per head (no split-K)
    mma_gemm3x<1><<<dim3(4, 8, 16), 256>>>(
        a0h, a0l, EMB, HDIM, wkth, wktl, HDIM, (long long)D_DRUG * HDIM, nullptr, 0,
        qkp, nullptr, nullptr, NHEAD * D_DRUG, D_DRUG,
        nullptr, 0, 0, 0, nullptr, 1.0f, HDIM, 1);

    // 5: attention
    attn_kernel<<<512, 256>>>(x_nodes, qkp, seg, xah, xal);

    // 6: vv per head + bv  (fused split-K4 -> a1 hi/lo)
    mma_gemm3x<0><<<dim3(1, 8, 64), 256>>>(
        xah, xal, NHEAD * D_DRUG, D_DRUG, wvh, wvl, D_DRUG, (long long)HDIM * D_DRUG,
        bv, HDIM,
        nullptr, a1h, a1l, EMB, HDIM,
        part, EMB, PSTR, HDIM, cnt + 2 * 128, 1.0f, 64, 4);

    // 7: G3 out = op @ Wo^T + bo  (fused split-K4 -> fp32 strided)
    mma_gemm3x<1><<<dim3(16, 8, 4), 256>>>(
        a1h, a1l, EMB, 0, woh, wol, EMB, 0, bo, 0,
        out, nullptr, nullptr, EMB + D_CELL, 0,
        part, EMB, PSTR, 0, cnt + 3 * 128, 1.0f, 256, 4);

    (void)n_in; (void)out_size;
}

// round 14
// speedup vs baseline: 1.0930x; 1.0930x over previous
#include <cuda_runtime.h>
#include <cuda_bf16.h>
#include <cstdint>

// ---------------------------------------------------------------------------
// Problem constants
// ---------------------------------------------------------------------------
#define BATCH   512
#define MAXLEN  128
#define D_DRUG  256
#define D_CELL  1024
#define NHEAD   16
#define HDIM    64
#define EMB     1024   // NHEAD*HDIM

// ---------------------------------------------------------------------------
// Scratch (device globals)
// ---------------------------------------------------------------------------
__device__ float g_qk  [BATCH * NHEAD * D_DRUG];
__device__ float g_part[4 * BATCH * EMB];
__device__ int   g_seg [BATCH + 1];

__device__ __nv_bfloat16 g_a0h[BATCH * EMB],   g_a0l[BATCH * EMB];
__device__ __nv_bfloat16 g_a1h[BATCH * EMB],   g_a1l[BATCH * EMB];
__device__ __nv_bfloat16 g_xah[BATCH * NHEAD * D_DRUG], g_xal[BATCH * NHEAD * D_DRUG];
__device__ __nv_bfloat16 g_wch[EMB * D_CELL],  g_wcl[EMB * D_CELL];
__device__ __nv_bfloat16 g_wqh[EMB * EMB],     g_wql[EMB * EMB];
__device__ __nv_bfloat16 g_woh[EMB * EMB],     g_wol[EMB * EMB];
__device__ __nv_bfloat16 g_wvh[EMB * D_DRUG],  g_wvl[EMB * D_DRUG];
__device__ __nv_bfloat16 g_wkth[NHEAD * D_DRUG * HDIM], g_wktl[NHEAD * D_DRUG * HDIM];

// ---------------------------------------------------------------------------
// Helpers
// ---------------------------------------------------------------------------
union F2U { float2 f; unsigned long long u; };
__device__ __forceinline__ void fma2(F2U &c, F2U a, F2U b) {
    asm("fma.rn.f32x2 %0, %1, %2, %0;" : "+l"(c.u) : "l"(a.u), "l"(b.u));
}

__device__ __forceinline__ uint32_t smem_u32(const void* p) {
    uint32_t a;
    asm("{ .reg .u64 t; cvta.to.shared.u64 t, %1; cvt.u32.u64 %0, t; }" : "=r"(a) : "l"(p));
    return a;
}

__device__ __forceinline__ void ldsm4(uint32_t &r0, uint32_t &r1, uint32_t &r2, uint32_t &r3,
                                      uint32_t a) {
    asm volatile("ldmatrix.sync.aligned.m8n8.x4.shared.b16 {%0,%1,%2,%3}, [%4];"
        : "=r"(r0), "=r"(r1), "=r"(r2), "=r"(r3) : "r"(a));
}

__device__ __forceinline__ void mma_bf16(float c[4], const uint32_t a[4],
                                         uint32_t b0, uint32_t b1) {
    asm volatile("mma.sync.aligned.m16n8k16.row.col.f32.bf16.bf16.f32 "
        "{%0,%1,%2,%3}, {%4,%5,%6,%7}, {%8,%9}, {%0,%1,%2,%3};"
        : "+f"(c[0]), "+f"(c[1]), "+f"(c[2]), "+f"(c[3])
        : "r"(a[0]), "r"(a[1]), "r"(a[2]), "r"(a[3]), "r"(b0), "r"(b1));
}

__device__ __forceinline__ uint32_t pack_bf16(float a, float b) {
    return (uint32_t)__bfloat16_as_ushort(__float2bfloat16(a))
         | ((uint32_t)__bfloat16_as_ushort(__float2bfloat16(b)) << 16);
}

#define CPA16(sm, gp) asm volatile("cp.async.cg.shared.global [%0], [%1], 16;" :: "r"(sm), "l"(gp))
#define CP_COMMIT()   asm volatile("cp.async.commit_group;" ::: "memory")
#define CP_WAIT0()    asm volatile("cp.async.wait_group 0;" ::: "memory")
#define CP_WAIT1()    asm volatile("cp.async.wait_group 1;" ::: "memory")

// ---------------------------------------------------------------------------
// Fused prep kernel
// ---------------------------------------------------------------------------
__device__ __forceinline__ void split4(const float4* s, uint2* hi, uint2* lo, int i)
{
    float4 v = s[i];
    __nv_bfloat16 h0 = __float2bfloat16(v.x), h1 = __float2bfloat16(v.y);
    __nv_bfloat16 h2 = __float2bfloat16(v.z), h3 = __float2bfloat16(v.w);
    uint2 H, L;
    H.x = (uint32_t)__bfloat16_as_ushort(h0) | ((uint32_t)__bfloat16_as_ushort(h1) << 16);
    H.y = (uint32_t)__bfloat16_as_ushort(h2) | ((uint32_t)__bfloat16_as_ushort(h3) << 16);
    L.x = pack_bf16(v.x - __bfloat162float(h0), v.y - __bfloat162float(h1));
    L.y = pack_bf16(v.z - __bfloat162float(h2), v.w - __bfloat162float(h3));
    hi[i] = H; lo[i] = L;
}

__global__ __launch_bounds__(256)
void prep_kernel(const float4* Wc, const float4* Wq, const float4* Wo,
                 const float4* Wv, const float4* cell, const float* Wk,
                 const void* guide, int n,
                 uint2* wch, uint2* wcl, uint2* wqh, uint2* wql,
                 uint2* woh, uint2* wol, uint2* wvh, uint2* wvl,
                 uint2* ah, uint2* al,
                 __nv_bfloat16* wkth, __nv_bfloat16* wktl,
                 int* seg, float4* outp)
{
    __shared__ float tile[32][33];
    int blk = blockIdx.x, t = threadIdx.x;

    if (blk < 3840) {
        int i = blk * 256 + t;
        if      (i < 262144)  split4(Wc, wch, wcl, i);
        else if (i < 524288)  split4(Wq, wqh, wql, i - 262144);
        else if (i < 786432)  split4(Wo, woh, wol, i - 524288);
        else if (i < 851968)  split4(Wv, wvh, wvl, i - 786432);
        else if (i < 983040)  split4(cell, ah, al, i - 851968);
    } else if (blk < 4096) {
        int b2 = blk - 3840;
        int nt = b2 & 7, dt = (b2 >> 3) & 1, h = b2 >> 4;
        int tx = t & 31, ty = t >> 5;
#pragma unroll
        for (int r = ty; r < 32; r += 8)
            tile[r][tx] = Wk[(long long)(h * 64 + dt * 32 + r) * D_DRUG + nt * 32 + tx];
        __syncthreads();
#pragma unroll
        for (int r = ty; r < 32; r += 8) {
            float v = tile[tx][r];
            __nv_bfloat16 hh = __float2bfloat16(v);
            long long o = (long long)h * (D_DRUG * HDIM)
                        + (long long)(nt * 32 + r) * HDIM + dt * 32 + tx;
            wkth[o] = hh;
            wktl[o] = __float2bfloat16(v - __bfloat162float(hh));
        }
    } else if (blk < 4099) {
        int g = (blk - 4096) * 256 + t;
        if (g <= BATCH) {
            const unsigned long long* g64 = (const unsigned long long*)guide;
            const int*                g32 = (const int*)guide;
            bool is64 = (g64[(n >> 1) - 1] <= 511ull);
            int lo2 = 0, hi2 = n;
            while (lo2 < hi2) {
                int mid = (lo2 + hi2) >> 1;
                long long v = is64 ? (long long)g64[mid] : (long long)g32[mid];
                if (v < (long long)g) lo2 = mid + 1; else hi2 = mid;
            }
            seg[g] = lo2;
        }
    } else {
        int i = (blk - 4099) * 256 + t;
        if (i < BATCH * (D_CELL / 4)) {
            int b = i >> 8, j = i & 255;
            outp[b * ((EMB + D_CELL) / 4) + (EMB / 4) + j] = cell[i];
        }
    }
}

// ---------------------------------------------------------------------------
// Split-K reduce (R9 proven version)
// ---------------------------------------------------------------------------
template <int MODE, int NS>
__global__ __launch_bounds__(256)
void reduce_k(const float4* __restrict__ part, const float* __restrict__ bias,
              float* __restrict__ outf, __nv_bfloat16* __restrict__ oh,
              __nv_bfloat16* __restrict__ ol, int ldc, float alpha)
{
    int i = blockIdx.x * 256 + threadIdx.x;
    if (i >= BATCH * (EMB / 4)) return;
    int b = i >> 8, j = i & 255;
    float4 p[NS];
#pragma unroll
    for (int k = 0; k < NS; k++) p[k] = part[k * (BATCH * EMB / 4) + i];
    float4 s = p[0];
#pragma unroll
    for (int k = 1; k < NS; k++) { s.x += p[k].x; s.y += p[k].y; s.z += p[k].z; s.w += p[k].w; }
    int col = j * 4;
    float4 bb = *(const float4*)(bias + col);
    float vx = alpha * (s.x + bb.x), vy = alpha * (s.y + bb.y);
    float vz = alpha * (s.z + bb.z), vw = alpha * (s.w + bb.w);
    if (MODE == 1) {
        *(float4*)(outf + (long long)b * ldc + col) = make_float4(vx, vy, vz, vw);
    } else {
        __nv_bfloat16 h0 = __float2bfloat16(vx), h1 = __float2bfloat16(vy);
        __nv_bfloat16 h2 = __float2bfloat16(vz), h3 = __float2bfloat16(vw);
        uint2 H, L;
        H.x = (uint32_t)__bfloat16_as_ushort(h0) | ((uint32_t)__bfloat16_as_ushort(h1) << 16);
        H.y = (uint32_t)__bfloat16_as_ushort(h2) | ((uint32_t)__bfloat16_as_ushort(h3) << 16);
        L.x = pack_bf16(vx - __bfloat162float(h0), vy - __bfloat162float(h1));
        L.y = pack_bf16(vz - __bfloat162float(h2), vw - __bfloat162float(h3));
        *(uint2*)(oh + (long long)b * ldc + col) = H;
        *(uint2*)(ol + (long long)b * ldc + col) = L;
    }
}

// ---------------------------------------------------------------------------
// bf16x3 MMA GEMM — 64x64 CTA, 256 thr, 8 warps = 2x2 grid of 32x32 warp
// tiles x 2 K-GROUPS (warp handles only kk = warp>>2 of each 32-k tile):
// -35% LDSM phases vs R9 at the same residency/warp count. Cross-group
// accumulator combine via one smem exchange in the epilogue.
// 2-stage cp.async, static 40KB smem (R9 layout).
// MODE 1: fp32 alpha*(acc+bias).  MODE 2: raw fp32 partial (zk-strided).
// ---------------------------------------------------------------------------
template <int MODE>
__global__ __launch_bounds__(256)
void mma_gemm3x(const __nv_bfloat16* __restrict__ Ah, const __nv_bfloat16* __restrict__ Al,
                int lda, long long sAz,
                const __nv_bfloat16* __restrict__ Wh, const __nv_bfloat16* __restrict__ Wl,
                int ldw, long long sWz,
                const float* __restrict__ bias, long long sbz,
                float* __restrict__ Cf,
                int ldc, long long sCz, float alpha, int Kslice, int nks, long long pstr)
{
    __shared__ __align__(16) char smraw[40960];

    int zb = blockIdx.z / nks, zk = blockIdx.z % nks;
    const __nv_bfloat16* Ah_ = Ah + (long long)zb * sAz + (long long)zk * Kslice;
    const __nv_bfloat16* Al_ = Al + (long long)zb * sAz + (long long)zk * Kslice;
    const __nv_bfloat16* Wh_ = Wh + (long long)zb * sWz + (long long)zk * Kslice;
    const __nv_bfloat16* Wl_ = Wl + (long long)zb * sWz + (long long)zk * Kslice;
    const float* bp = bias ? bias + (long long)zb * sbz : nullptr;
    long long coff = (MODE == 2) ? ((long long)zk * pstr + (long long)zb * sCz)
                                 : ((long long)zb * sCz);

    int tid = threadIdx.x, lane = tid & 31, warp = tid >> 5;
    int wk = warp >> 2;                 // k-group (0: k[0,16), 1: k[16,32) of each tile)
    int wm = (warp >> 1) & 1, wn = warp & 1;   // 2x2 grid of 32x32 warp tiles
    int m0 = blockIdx.y * 64, n0 = blockIdx.x * 64;

    int lr = tid >> 2;
    int lq = (tid & 3) * 8;
    int lo = lr * 80 + (tid & 3) * 16;

    const __nv_bfloat16* pAh = Ah_ + (long long)(m0 + lr) * lda + lq;
    const __nv_bfloat16* pAl = Al_ + (long long)(m0 + lr) * lda + lq;
    const __nv_bfloat16* pWh = Wh_ + (long long)(n0 + lr) * ldw + lq;
    const __nv_bfloat16* pWl = Wl_ + (long long)(n0 + lr) * ldw + lq;

    uint32_t smb = smem_u32(smraw);

    auto issue = [&](uint32_t so, int k0) {
        CPA16(smb + so + lo,          (const char*)(pAh + k0));
        CPA16(smb + so + 5120  + lo,  (const char*)(pAl + k0));
        CPA16(smb + so + 10240 + lo,  (const char*)(pWh + k0));
        CPA16(smb + so + 15360 + lo,  (const char*)(pWl + k0));
        CP_COMMIT();
    };

    float acc[2][4][4];
#pragma unroll
    for (int s = 0; s < 2; s++)
#pragma unroll
        for (int nb = 0; nb < 4; nb++)
#pragma unroll
            for (int i = 0; i < 4; i++) acc[s][nb][i] = 0.f;

    // fragment bases with the k-group offset folded in (kk = wk fixed)
    uint32_t aBase = smb + (uint32_t)((wm * 32 + (lane & 15)) * 80
                   + ((lane >> 4) & 1) * 16 + wk * 32);
    uint32_t bBase = smb + 10240u +
        (uint32_t)((wn * 32 + ((lane >> 4) & 1) * 8 + (lane & 7)) * 80
                   + ((lane >> 3) & 1) * 16 + wk * 32);

    int NT = Kslice / 32;
    issue(0, 0);
    if (NT > 1) issue(20480, 32);

    for (int t = 0; t < NT; t++) {
        if (t + 1 < NT) { CP_WAIT1(); } else { CP_WAIT0(); }
        __syncthreads();

        uint32_t bufo = (uint32_t)(t & 1) * 20480u;
        uint32_t ah[2][4], alr[2][4];
#pragma unroll
        for (int s = 0; s < 2; s++) {
            uint32_t ad = aBase + bufo + (uint32_t)(s * 1280);
            ldsm4(ah[s][0], ah[s][1], ah[s][2], ah[s][3], ad);
            ldsm4(alr[s][0], alr[s][1], alr[s][2], alr[s][3], ad + 5120u);
        }
        uint32_t bh[4][2], blr[4][2];
#pragma unroll
        for (int p = 0; p < 2; p++) {
            uint32_t bd = bBase + bufo + (uint32_t)(p * 1280);
            ldsm4(bh[2*p][0], bh[2*p][1], bh[2*p+1][0], bh[2*p+1][1], bd);
            ldsm4(blr[2*p][0], blr[2*p][1], blr[2*p+1][0], blr[2*p+1][1], bd + 5120u);
        }
        // 24 MMAs per warp per tile, product-major, 8 independent chains
#pragma unroll
        for (int s = 0; s < 2; s++)
#pragma unroll
            for (int nb = 0; nb < 4; nb++)
                mma_bf16(acc[s][nb], ah[s], bh[nb][0], bh[nb][1]);
#pragma unroll
        for (int s = 0; s < 2; s++)
#pragma unroll
            for (int nb = 0; nb < 4; nb++)
                mma_bf16(acc[s][nb], ah[s], blr[nb][0], blr[nb][1]);
#pragma unroll
        for (int s = 0; s < 2; s++)
#pragma unroll
            for (int nb = 0; nb < 4; nb++)
                mma_bf16(acc[s][nb], alr[s], bh[nb][0], bh[nb][1]);

        __syncthreads();
        if (t + 2 < NT) issue((uint32_t)(t & 1) * 20480u, (t + 2) * 32);
    }

    // cross-k-group combine: kg1 stores to smem, kg0 adds (row pad 68 words)
    int erow = lane >> 2;
    int ecol = (lane & 3) * 2;
    float* red = (float*)smraw;
    if (wk == 1) {
#pragma unroll
        for (int s = 0; s < 2; s++) {
            int r0 = wm * 32 + s * 16 + erow;
#pragma unroll
            for (int nb = 0; nb < 4; nb++) {
                int col = wn * 32 + nb * 8 + ecol;
                *(float2*)(red + r0 * 68 + col)       = make_float2(acc[s][nb][0], acc[s][nb][1]);
                *(float2*)(red + (r0 + 8) * 68 + col) = make_float2(acc[s][nb][2], acc[s][nb][3]);
            }
        }
    }
    __syncthreads();
    if (wk != 0) return;

#pragma unroll
    for (int s = 0; s < 2; s++) {
        int rl = wm * 32 + s * 16 + erow;
        int r0 = m0 + rl;
#pragma unroll
        for (int nb = 0; nb < 4; nb++) {
            int cl = wn * 32 + nb * 8 + ecol;
            int col = n0 + cl;
            float2 o0 = *(const float2*)(red + rl * 68 + cl);
            float2 o1 = *(const float2*)(red + (rl + 8) * 68 + cl);
            float v00 = acc[s][nb][0] + o0.x, v01 = acc[s][nb][1] + o0.y;
            float v10 = acc[s][nb][2] + o1.x, v11 = acc[s][nb][3] + o1.y;
            if (MODE == 2) {
                *(float2*)(Cf + coff + (long long)r0 * ldc + col)       = make_float2(v00, v01);
                *(float2*)(Cf + coff + (long long)(r0 + 8) * ldc + col) = make_float2(v10, v11);
            } else {
                float b0 = bp ? bp[col] : 0.f;
                float b1 = bp ? bp[col + 1] : 0.f;
                *(float2*)(Cf + coff + (long long)r0 * ldc + col)
                    = make_float2(alpha * (v00 + b0), alpha * (v01 + b1));
                *(float2*)(Cf + coff + (long long)(r0 + 8) * ldc + col)
                    = make_float2(alpha * (v10 + b0), alpha * (v11 + b1));
            }
        }
    }
}

// ---------------------------------------------------------------------------
// Fused attention (R10/R11 version — online softmax, col-sliced xa)
// ---------------------------------------------------------------------------
__global__ __launch_bounds__(256)
void attn_kernel(const float* __restrict__ x,
                 const float* __restrict__ qk,
                 const int*   __restrict__ seg,
                 __nv_bfloat16* __restrict__ xah,
                 __nv_bfloat16* __restrict__ xal)
{
    __shared__ float qks[16 * 260];
    __shared__ float xs [16 * 260];
    __shared__ float sw [16 * 20];
    __shared__ float sscale[16];
    __shared__ float sD[16];

    int b = blockIdx.x;
    int t = threadIdx.x;
    int s0 = seg[b];
    int len = seg[b + 1] - s0;
    if (len > MAXLEN) len = MAXLEN;

    const float4* qk4 = (const float4*)(qk + (long long)b * (NHEAD * D_DRUG));
#pragma unroll
    for (int r = 0; r < 4; r++) {
        int idx = t + r * 256;
        int h = idx >> 6, jj = idx & 63;
        *(float4*)&qks[h * 260 + jj * 4] = qk4[idx];
    }
    __syncthreads();

    int h  = t >> 4;
    int mm = t & 15;
    int w2 = t >> 5, lane = t & 31;
    int hx = lane >> 1, cx = lane & 1;
    int j0x = w2 * 32 + cx * 16;

    float M = -3.0e38f, D = 0.f;
    F2U acc[8];
#pragma unroll
    for (int i = 0; i < 8; i++) acc[i].f = make_float2(0.f, 0.f);

    for (int m0 = 0; m0 < len; m0 += 16) {
        int nm = len - m0; if (nm > 16) nm = 16;
#pragma unroll
        for (int r = 0; r < 4; r++) {
            int idx = t + r * 256;
            int row = idx >> 6, jj = idx & 63;
            if (row < nm)
                *(float4*)&xs[row * 260 + jj * 4] =
                    *(const float4*)(x + (long long)(s0 + m0 + row) * D_DRUG + jj * 4);
        }
        __syncthreads();

        float myscore = -3.0e38f;
        if (mm < nm) {
            const float* qp = &qks[h * 260];
            const float* xp = &xs[mm * 260];
            F2U a0, a1;
            a0.f = make_float2(0.f, 0.f);
            a1.f = make_float2(0.f, 0.f);
#pragma unroll
            for (int j = 0; j < 256; j += 8) {
                float4 q0 = *(const float4*)(qp + j);
                float4 x0 = *(const float4*)(xp + j);
                float4 q1 = *(const float4*)(qp + j + 4);
                float4 x1 = *(const float4*)(xp + j + 4);
                F2U aa, bb;
                aa.f = make_float2(q0.x, q0.y); bb.f = make_float2(x0.x, x0.y); fma2(a0, aa, bb);
                aa.f = make_float2(q0.z, q0.w); bb.f = make_float2(x0.z, x0.w); fma2(a1, aa, bb);
                aa.f = make_float2(q1.x, q1.y); bb.f = make_float2(x1.x, x1.y); fma2(a0, aa, bb);
                aa.f = make_float2(q1.z, q1.w); bb.f = make_float2(x1.z, x1.w); fma2(a1, aa, bb);
            }
            myscore = a0.f.x + a0.f.y + a1.f.x + a1.f.y;
        }

        float tmax = myscore;
#pragma unroll
        for (int o = 1; o < 16; o <<= 1)
            tmax = fmaxf(tmax, __shfl_xor_sync(0xffffffffu, tmax, o));
        float newM = fmaxf(M, tmax);
        float scale = __expf(M - newM);
        float w = (mm < nm) ? __expf(myscore - newM) : 0.f;
        float ws = w;
#pragma unroll
        for (int o = 1; o < 16; o <<= 1)
            ws += __shfl_xor_sync(0xffffffffu, ws, o);
        D = D * scale + ws;
        M = newM;
        sw[h * 20 + mm] = w;
        if (mm == 0) sscale[h] = scale;
        __syncthreads();

        float sc2 = sscale[hx];
#pragma unroll
        for (int i = 0; i < 8; i++) { acc[i].f.x *= sc2; acc[i].f.y *= sc2; }
        const float* swr = &sw[hx * 20];
        for (int i = 0; i < nm; i++) {
            float a = swr[i];
            F2U ad; ad.f = make_float2(a, a);
            const float* xr = &xs[i * 260 + j0x];
#pragma unroll
            for (int r = 0; r < 4; r++) {
                float4 v = *(const float4*)(xr + r * 4);
                F2U b0, b1;
                b0.f = make_float2(v.x, v.y);
                b1.f = make_float2(v.z, v.w);
                fma2(acc[2 * r], ad, b0);
                fma2(acc[2 * r + 1], ad, b1);
            }
        }
        __syncthreads();
    }

    if (mm == 0) sD[h] = D;
    __syncthreads();

    float Df = sD[hx];
    float inv = (Df > 0.f) ? (1.0f / Df) : 0.f;
    long long base = (long long)b * (NHEAD * D_DRUG) + hx * D_DRUG + j0x;
#pragma unroll
    for (int i = 0; i < 8; i++) {
        float va = acc[i].f.x * inv, vb = acc[i].f.y * inv;
        __nv_bfloat16 ha = __float2bfloat16(va), hb = __float2bfloat16(vb);
        uint32_t ph = (uint32_t)__bfloat16_as_ushort(ha)
                    | ((uint32_t)__bfloat16_as_ushort(hb) << 16);
        uint32_t pl = pack_bf16(va - __bfloat162float(ha), vb - __bfloat162float(hb));
        *(uint32_t*)(xah + base + i * 2) = ph;
        *(uint32_t*)(xal + base + i * 2) = pl;
    }
}

// ---------------------------------------------------------------------------
// Launch
// ---------------------------------------------------------------------------
extern "C" void kernel_launch(void* const* d_in, const int* in_sizes, int n_in,
                              void* d_out, int out_size)
{
    const float* x_nodes = (const float*)d_in[0];
    const float* cell    = (const float*)d_in[1];
    const float* Wq      = (const float*)d_in[2];
    const float* bq      = (const float*)d_in[3];
    const float* Wk      = (const float*)d_in[4];
    /* bk cancels in softmax */
    const float* Wv      = (const float*)d_in[6];
    const float* bv      = (const float*)d_in[7];
    const float* Wo      = (const float*)d_in[8];
    const float* bo      = (const float*)d_in[9];
    const float* Wc      = (const float*)d_in[10];
    const float* bc      = (const float*)d_in[11];
    const void*  guide   = d_in[12];
    float*       out     = (float*)d_out;

    int N = in_sizes[12];

    float *qkp, *part; int* seg;
    __nv_bfloat16 *a0h, *a0l, *a1h, *a1l, *xah, *xal;
    __nv_bfloat16 *wch, *wcl, *wqh, *wql, *woh, *wol, *wvh, *wvl, *wkth, *wktl;
    cudaGetSymbolAddress((void**)&qkp,  g_qk);
    cudaGetSymbolAddress((void**)&part, g_part);
    cudaGetSymbolAddress((void**)&seg,  g_seg);
    cudaGetSymbolAddress((void**)&a0h,  g_a0h);
    cudaGetSymbolAddress((void**)&a0l,  g_a0l);
    cudaGetSymbolAddress((void**)&a1h,  g_a1h);
    cudaGetSymbolAddress((void**)&a1l,  g_a1l);
    cudaGetSymbolAddress((void**)&xah,  g_xah);
    cudaGetSymbolAddress((void**)&xal,  g_xal);
    cudaGetSymbolAddress((void**)&wch,  g_wch);
    cudaGetSymbolAddress((void**)&wcl,  g_wcl);
    cudaGetSymbolAddress((void**)&wqh,  g_wqh);
    cudaGetSymbolAddress((void**)&wql,  g_wql);
    cudaGetSymbolAddress((void**)&woh,  g_woh);
    cudaGetSymbolAddress((void**)&wol,  g_wol);
    cudaGetSymbolAddress((void**)&wvh,  g_wvh);
    cudaGetSymbolAddress((void**)&wvl,  g_wvl);
    cudaGetSymbolAddress((void**)&wkth, g_wkth);
    cudaGetSymbolAddress((void**)&wktl, g_wktl);

    const long long PSTR = (long long)BATCH * EMB;

    // 1: fused prep
    prep_kernel<<<4611, 256>>>((const float4*)Wc, (const float4*)Wq, (const float4*)Wo,
                               (const float4*)Wv, (const float4*)cell, Wk, guide, N,
                               (uint2*)wch, (uint2*)wcl, (uint2*)wqh, (uint2*)wql,
                               (uint2*)woh, (uint2*)wol, (uint2*)wvh, (uint2*)wvl,
                               (uint2*)a0h, (uint2*)a0l, wkth, wktl, seg, (float4*)out);

    // 2: G1 cq = cell @ Wc^T (split-K4)
    mma_gemm3x<2><<<dim3(16, 8, 4), 256>>>(
        a0h, a0l, D_CELL, 0, wch, wcl, D_CELL, 0, nullptr, 0,
        part, EMB, 0, 1.0f, 256, 4, PSTR);
    // 3: reduce +bc -> a1 hi/lo
    reduce_k<0, 4><<<512, 256>>>((const float4*)part, bc, nullptr, a1h, a1l, EMB, 1.0f);

    // 4 (profiled slot): G2 q = cq @ Wq^T (split-K4)
    mma_gemm3x<2><<<dim3(16, 8, 4), 256>>>(
        a1h, a1l, EMB, 0, wqh, wql, EMB, 0, nullptr, 0,
        part, EMB, 0, 1.0f, 256, 4, PSTR);
    // 5: reduce (+bq)*0.125 -> a0 hi/lo
    reduce_k<0, 4><<<512, 256>>>((const float4*)part, bq, nullptr, a0h, a0l, EMB, 0.125f);

    // 6: qk = q @ WkT per head
    mma_gemm3x<1><<<dim3(4, 8, 16), 256>>>(
        a0h, a0l, EMB, HDIM, wkth, wktl, HDIM, (long long)D_DRUG * HDIM, nullptr, 0,
        qkp, NHEAD * D_DRUG, D_DRUG, 1.0f, HDIM, 1, 0);

    // 7: attention
    attn_kernel<<<512, 256>>>(x_nodes, qkp, seg, xah, xal);

    // 8: vv per head (split-K4)
    mma_gemm3x<2><<<dim3(1, 8, 64), 256>>>(
        xah, xal, NHEAD * D_DRUG, D_DRUG, wvh, wvl, D_DRUG, (long long)HDIM * D_DRUG,
        nullptr, 0, part, EMB, HDIM, 1.0f, 64, 4, PSTR);
    // 9: reduce +bv -> a1 hi/lo
    reduce_k<0, 4><<<512, 256>>>((const float4*)part, bv, nullptr, a1h, a1l, EMB, 1.0f);

    // 10: G3 out = op @ Wo^T (split-K4)
    mma_gemm3x<2><<<dim3(16, 8, 4), 256>>>(
        a1h, a1l, EMB, 0, woh, wol, EMB, 0, nullptr, 0,
        part, EMB, 0, 1.0f, 256, 4, PSTR);
    // 11: reduce +bo -> fp32 strided into out
    reduce_k<1, 4><<<512, 256>>>((const float4*)part, bo, out, nullptr, nullptr,
                                 EMB + D_CELL, 1.0f);

    (void)n_in; (void)out_size;
}

// round 15
// speedup vs baseline: 1.0998x; 1.0062x over previous
#include <cuda_runtime.h>
#include <cuda_bf16.h>
#include <cstdint>

// ---------------------------------------------------------------------------
// Problem constants
// ---------------------------------------------------------------------------
#define BATCH   512
#define MAXLEN  128
#define D_DRUG  256
#define D_CELL  1024
#define NHEAD   16
#define HDIM    64
#define EMB     1024   // NHEAD*HDIM

// ---------------------------------------------------------------------------
// Scratch (device globals)
// ---------------------------------------------------------------------------
__device__ float g_qk  [BATCH * NHEAD * D_DRUG];
__device__ float g_part[4 * BATCH * EMB];
__device__ int   g_seg [BATCH + 1];

__device__ __nv_bfloat16 g_a0h[BATCH * EMB],   g_a0l[BATCH * EMB];
__device__ __nv_bfloat16 g_a1h[BATCH * EMB],   g_a1l[BATCH * EMB];
__device__ __nv_bfloat16 g_xah[BATCH * NHEAD * D_DRUG], g_xal[BATCH * NHEAD * D_DRUG];
__device__ __nv_bfloat16 g_wch[EMB * D_CELL],  g_wcl[EMB * D_CELL];
__device__ __nv_bfloat16 g_wqh[EMB * EMB],     g_wql[EMB * EMB];
__device__ __nv_bfloat16 g_woh[EMB * EMB],     g_wol[EMB * EMB];
__device__ __nv_bfloat16 g_wvh[EMB * D_DRUG],  g_wvl[EMB * D_DRUG];
__device__ __nv_bfloat16 g_wkth[NHEAD * D_DRUG * HDIM], g_wktl[NHEAD * D_DRUG * HDIM];

// ---------------------------------------------------------------------------
// Helpers
// ---------------------------------------------------------------------------
union F2U { float2 f; unsigned long long u; };
__device__ __forceinline__ void fma2(F2U &c, F2U a, F2U b) {
    asm("fma.rn.f32x2 %0, %1, %2, %0;" : "+l"(c.u) : "l"(a.u), "l"(b.u));
}

__device__ __forceinline__ uint32_t smem_u32(const void* p) {
    uint32_t a;
    asm("{ .reg .u64 t; cvta.to.shared.u64 t, %1; cvt.u32.u64 %0, t; }" : "=r"(a) : "l"(p));
    return a;
}

__device__ __forceinline__ void ldsm4(uint32_t &r0, uint32_t &r1, uint32_t &r2, uint32_t &r3,
                                      uint32_t a) {
    asm volatile("ldmatrix.sync.aligned.m8n8.x4.shared.b16 {%0,%1,%2,%3}, [%4];"
        : "=r"(r0), "=r"(r1), "=r"(r2), "=r"(r3) : "r"(a));
}

__device__ __forceinline__ void mma_bf16(float c[4], const uint32_t a[4],
                                         uint32_t b0, uint32_t b1) {
    asm volatile("mma.sync.aligned.m16n8k16.row.col.f32.bf16.bf16.f32 "
        "{%0,%1,%2,%3}, {%4,%5,%6,%7}, {%8,%9}, {%0,%1,%2,%3};"
        : "+f"(c[0]), "+f"(c[1]), "+f"(c[2]), "+f"(c[3])
        : "r"(a[0]), "r"(a[1]), "r"(a[2]), "r"(a[3]), "r"(b0), "r"(b1));
}

__device__ __forceinline__ uint32_t pack_bf16(float a, float b) {
    return (uint32_t)__bfloat16_as_ushort(__float2bfloat16(a))
         | ((uint32_t)__bfloat16_as_ushort(__float2bfloat16(b)) << 16);
}

#define CPA16(sm, gp) asm volatile("cp.async.cg.shared.global [%0], [%1], 16;" :: "r"(sm), "l"(gp))
#define CP_COMMIT()   asm volatile("cp.async.commit_group;" ::: "memory")
#define CP_WAIT0()    asm volatile("cp.async.wait_group 0;" ::: "memory")
#define CP_WAIT1()    asm volatile("cp.async.wait_group 1;" ::: "memory")

__device__ __forceinline__ void split4(const float4* s, uint2* hi, uint2* lo, int i)
{
    float4 v = s[i];
    __nv_bfloat16 h0 = __float2bfloat16(v.x), h1 = __float2bfloat16(v.y);
    __nv_bfloat16 h2 = __float2bfloat16(v.z), h3 = __float2bfloat16(v.w);
    uint2 H, L;
    H.x = (uint32_t)__bfloat16_as_ushort(h0) | ((uint32_t)__bfloat16_as_ushort(h1) << 16);
    H.y = (uint32_t)__bfloat16_as_ushort(h2) | ((uint32_t)__bfloat16_as_ushort(h3) << 16);
    L.x = pack_bf16(v.x - __bfloat162float(h0), v.y - __bfloat162float(h1));
    L.y = pack_bf16(v.z - __bfloat162float(h2), v.w - __bfloat162float(h3));
    hi[i] = H; lo[i] = L;
}

// ---------------------------------------------------------------------------
// prep-A: only what G1 needs — Wc split (1024 blocks) + cell split (512)
// ---------------------------------------------------------------------------
__global__ __launch_bounds__(256)
void prepA_kernel(const float4* Wc, const float4* cell,
                  uint2* wch, uint2* wcl, uint2* ah, uint2* al)
{
    int i = blockIdx.x * 256 + threadIdx.x;
    if (i < 262144)       split4(Wc, wch, wcl, i);
    else if (i < 393216)  split4(cell, ah, al, i - 262144);
}

// ---------------------------------------------------------------------------
// G1 GEMM (split-K4, R14 k-group kernel, hardcoded params) FUSED with
// prep-B (Wq/Wo/Wv splits, WkT, seg, copy_cell) as extra grid blocks.
// blocks [0,512):   GEMM  part[zk] = cell_split @ Wc_split^T slices
// blocks [512, 3587): prep-B (independent of G1's outputs)
// ---------------------------------------------------------------------------
__global__ __launch_bounds__(256)
void g1_fused(const __nv_bfloat16* __restrict__ Ah, const __nv_bfloat16* __restrict__ Al,
              const __nv_bfloat16* __restrict__ Wh, const __nv_bfloat16* __restrict__ Wl,
              float* __restrict__ part, long long pstr,
              const float4* Wq, const float4* Wo, const float4* Wv, const float4* cell,
              const float* Wk, const void* guide, int n,
              uint2* wqh, uint2* wql, uint2* woh, uint2* wol,
              uint2* wvh, uint2* wvl,
              __nv_bfloat16* wkth, __nv_bfloat16* wktl,
              int* seg, float4* outp)
{
    __shared__ __align__(16) char smraw[40960];
    int gx = blockIdx.x, tid = threadIdx.x;

    if (gx >= 512) {
        // ---- prep-B ----
        int pb = gx - 512;
        if (pb < 2048) {
            int i = pb * 256 + tid;
            if (i < 262144) split4(Wq, wqh, wql, i);
            else            split4(Wo, woh, wol, i - 262144);
        } else if (pb < 2304) {
            int i = (pb - 2048) * 256 + tid;
            split4(Wv, wvh, wvl, i);           // 65536 float4
        } else if (pb < 2560) {
            float (*tile)[33] = (float (*)[33])smraw;
            int b2 = pb - 2304;
            int nt = b2 & 7, dt = (b2 >> 3) & 1, h = b2 >> 4;
            int tx = tid & 31, ty = tid >> 5;
#pragma unroll
            for (int r = ty; r < 32; r += 8)
                tile[r][tx] = Wk[(long long)(h * 64 + dt * 32 + r) * D_DRUG + nt * 32 + tx];
            __syncthreads();
#pragma unroll
            for (int r = ty; r < 32; r += 8) {
                float v = tile[tx][r];
                __nv_bfloat16 hh = __float2bfloat16(v);
                long long o = (long long)h * (D_DRUG * HDIM)
                            + (long long)(nt * 32 + r) * HDIM + dt * 32 + tx;
                wkth[o] = hh;
                wktl[o] = __float2bfloat16(v - __bfloat162float(hh));
            }
        } else if (pb < 2563) {
            int g = (pb - 2560) * 256 + tid;
            if (g <= BATCH) {
                const unsigned long long* g64 = (const unsigned long long*)guide;
                const int*                g32 = (const int*)guide;
                bool is64 = (g64[(n >> 1) - 1] <= 511ull);
                int lo2 = 0, hi2 = n;
                while (lo2 < hi2) {
                    int mid = (lo2 + hi2) >> 1;
                    long long v = is64 ? (long long)g64[mid] : (long long)g32[mid];
                    if (v < (long long)g) lo2 = mid + 1; else hi2 = mid;
                }
                seg[g] = lo2;
            }
        } else {
            int i = (pb - 2563) * 256 + tid;
            if (i < BATCH * (D_CELL / 4)) {
                int b = i >> 8, j = i & 255;
                outp[b * ((EMB + D_CELL) / 4) + (EMB / 4) + j] = cell[i];
            }
        }
        return;
    }

    // ---- G1 GEMM CTA: x = n-tile (16), y = m-tile (8), zk (4) ----
    int xg = gx & 15, yg = (gx >> 4) & 7, zk = gx >> 7;
    const int Kslice = 256;
    const __nv_bfloat16* Ah_ = Ah + (long long)zk * Kslice;
    const __nv_bfloat16* Al_ = Al + (long long)zk * Kslice;
    const __nv_bfloat16* Wh_ = Wh + (long long)zk * Kslice;
    const __nv_bfloat16* Wl_ = Wl + (long long)zk * Kslice;
    long long coff = (long long)zk * pstr;

    int lane = tid & 31, warp = tid >> 5;
    int wk = warp >> 2;
    int wm = (warp >> 1) & 1, wn = warp & 1;
    int m0 = yg * 64, n0 = xg * 64;

    int lr = tid >> 2;
    int lq = (tid & 3) * 8;
    int lo = lr * 80 + (tid & 3) * 16;

    const __nv_bfloat16* pAh = Ah_ + (long long)(m0 + lr) * D_CELL + lq;
    const __nv_bfloat16* pAl = Al_ + (long long)(m0 + lr) * D_CELL + lq;
    const __nv_bfloat16* pWh = Wh_ + (long long)(n0 + lr) * D_CELL + lq;
    const __nv_bfloat16* pWl = Wl_ + (long long)(n0 + lr) * D_CELL + lq;

    uint32_t smb = smem_u32(smraw);

    auto issue = [&](uint32_t so, int k0) {
        CPA16(smb + so + lo,          (const char*)(pAh + k0));
        CPA16(smb + so + 5120  + lo,  (const char*)(pAl + k0));
        CPA16(smb + so + 10240 + lo,  (const char*)(pWh + k0));
        CPA16(smb + so + 15360 + lo,  (const char*)(pWl + k0));
        CP_COMMIT();
    };

    float acc[2][4][4];
#pragma unroll
    for (int s = 0; s < 2; s++)
#pragma unroll
        for (int nb = 0; nb < 4; nb++)
#pragma unroll
            for (int i = 0; i < 4; i++) acc[s][nb][i] = 0.f;

    uint32_t aBase = smb + (uint32_t)((wm * 32 + (lane & 15)) * 80
                   + ((lane >> 4) & 1) * 16 + wk * 32);
    uint32_t bBase = smb + 10240u +
        (uint32_t)((wn * 32 + ((lane >> 4) & 1) * 8 + (lane & 7)) * 80
                   + ((lane >> 3) & 1) * 16 + wk * 32);

    const int NT = Kslice / 32;
    issue(0, 0);
    issue(20480, 32);

    for (int t = 0; t < NT; t++) {
        if (t + 1 < NT) { CP_WAIT1(); } else { CP_WAIT0(); }
        __syncthreads();

        uint32_t bufo = (uint32_t)(t & 1) * 20480u;
        uint32_t ah[2][4], alr[2][4];
#pragma unroll
        for (int s = 0; s < 2; s++) {
            uint32_t ad = aBase + bufo + (uint32_t)(s * 1280);
            ldsm4(ah[s][0], ah[s][1], ah[s][2], ah[s][3], ad);
            ldsm4(alr[s][0], alr[s][1], alr[s][2], alr[s][3], ad + 5120u);
        }
        uint32_t bh[4][2], blr[4][2];
#pragma unroll
        for (int p = 0; p < 2; p++) {
            uint32_t bd = bBase + bufo + (uint32_t)(p * 1280);
            ldsm4(bh[2*p][0], bh[2*p][1], bh[2*p+1][0], bh[2*p+1][1], bd);
            ldsm4(blr[2*p][0], blr[2*p][1], blr[2*p+1][0], blr[2*p+1][1], bd + 5120u);
        }
#pragma unroll
        for (int s = 0; s < 2; s++)
#pragma unroll
            for (int nb = 0; nb < 4; nb++)
                mma_bf16(acc[s][nb], ah[s], bh[nb][0], bh[nb][1]);
#pragma unroll
        for (int s = 0; s < 2; s++)
#pragma unroll
            for (int nb = 0; nb < 4; nb++)
                mma_bf16(acc[s][nb], ah[s], blr[nb][0], blr[nb][1]);
#pragma unroll
        for (int s = 0; s < 2; s++)
#pragma unroll
            for (int nb = 0; nb < 4; nb++)
                mma_bf16(acc[s][nb], alr[s], bh[nb][0], bh[nb][1]);

        __syncthreads();
        if (t + 2 < NT) issue((uint32_t)(t & 1) * 20480u, (t + 2) * 32);
    }

    int erow = lane >> 2;
    int ecol = (lane & 3) * 2;
    float* red = (float*)smraw;
    if (wk == 1) {
#pragma unroll
        for (int s = 0; s < 2; s++) {
            int r0 = wm * 32 + s * 16 + erow;
#pragma unroll
            for (int nb = 0; nb < 4; nb++) {
                int col = wn * 32 + nb * 8 + ecol;
                *(float2*)(red + r0 * 68 + col)       = make_float2(acc[s][nb][0], acc[s][nb][1]);
                *(float2*)(red + (r0 + 8) * 68 + col) = make_float2(acc[s][nb][2], acc[s][nb][3]);
            }
        }
    }
    __syncthreads();
    if (wk != 0) return;

#pragma unroll
    for (int s = 0; s < 2; s++) {
        int rl = wm * 32 + s * 16 + erow;
        int r0 = m0 + rl;
#pragma unroll
        for (int nb = 0; nb < 4; nb++) {
            int cl = wn * 32 + nb * 8 + ecol;
            int col = n0 + cl;
            float2 o0 = *(const float2*)(red + rl * 68 + cl);
            float2 o1 = *(const float2*)(red + (rl + 8) * 68 + cl);
            *(float2*)(part + coff + (long long)r0 * EMB + col)
                = make_float2(acc[s][nb][0] + o0.x, acc[s][nb][1] + o0.y);
            *(float2*)(part + coff + (long long)(r0 + 8) * EMB + col)
                = make_float2(acc[s][nb][2] + o1.x, acc[s][nb][3] + o1.y);
        }
    }
}

// ---------------------------------------------------------------------------
// Split-K reduce (R9/R14 proven version)
// ---------------------------------------------------------------------------
template <int MODE, int NS>
__global__ __launch_bounds__(256)
void reduce_k(const float4* __restrict__ part, const float* __restrict__ bias,
              float* __restrict__ outf, __nv_bfloat16* __restrict__ oh,
              __nv_bfloat16* __restrict__ ol, int ldc, float alpha)
{
    int i = blockIdx.x * 256 + threadIdx.x;
    if (i >= BATCH * (EMB / 4)) return;
    int b = i >> 8, j = i & 255;
    float4 p[NS];
#pragma unroll
    for (int k = 0; k < NS; k++) p[k] = part[k * (BATCH * EMB / 4) + i];
    float4 s = p[0];
#pragma unroll
    for (int k = 1; k < NS; k++) { s.x += p[k].x; s.y += p[k].y; s.z += p[k].z; s.w += p[k].w; }
    int col = j * 4;
    float4 bb = *(const float4*)(bias + col);
    float vx = alpha * (s.x + bb.x), vy = alpha * (s.y + bb.y);
    float vz = alpha * (s.z + bb.z), vw = alpha * (s.w + bb.w);
    if (MODE == 1) {
        *(float4*)(outf + (long long)b * ldc + col) = make_float4(vx, vy, vz, vw);
    } else {
        __nv_bfloat16 h0 = __float2bfloat16(vx), h1 = __float2bfloat16(vy);
        __nv_bfloat16 h2 = __float2bfloat16(vz), h3 = __float2bfloat16(vw);
        uint2 H, L;
        H.x = (uint32_t)__bfloat16_as_ushort(h0) | ((uint32_t)__bfloat16_as_ushort(h1) << 16);
        H.y = (uint32_t)__bfloat16_as_ushort(h2) | ((uint32_t)__bfloat16_as_ushort(h3) << 16);
        L.x = pack_bf16(vx - __bfloat162float(h0), vy - __bfloat162float(h1));
        L.y = pack_bf16(vz - __bfloat162float(h2), vw - __bfloat162float(h3));
        *(uint2*)(oh + (long long)b * ldc + col) = H;
        *(uint2*)(ol + (long long)b * ldc + col) = L;
    }
}

// ---------------------------------------------------------------------------
// bf16x3 MMA GEMM — R14 k-group kernel (measured equal-best: 19.0 us)
// ---------------------------------------------------------------------------
template <int MODE>
__global__ __launch_bounds__(256)
void mma_gemm3x(const __nv_bfloat16* __restrict__ Ah, const __nv_bfloat16* __restrict__ Al,
                int lda, long long sAz,
                const __nv_bfloat16* __restrict__ Wh, const __nv_bfloat16* __restrict__ Wl,
                int ldw, long long sWz,
                const float* __restrict__ bias, long long sbz,
                float* __restrict__ Cf,
                int ldc, long long sCz, float alpha, int Kslice, int nks, long long pstr)
{
    __shared__ __align__(16) char smraw[40960];

    int zb = blockIdx.z / nks, zk = blockIdx.z % nks;
    const __nv_bfloat16* Ah_ = Ah + (long long)zb * sAz + (long long)zk * Kslice;
    const __nv_bfloat16* Al_ = Al + (long long)zb * sAz + (long long)zk * Kslice;
    const __nv_bfloat16* Wh_ = Wh + (long long)zb * sWz + (long long)zk * Kslice;
    const __nv_bfloat16* Wl_ = Wl + (long long)zb * sWz + (long long)zk * Kslice;
    const float* bp = bias ? bias + (long long)zb * sbz : nullptr;
    long long coff = (MODE == 2) ? ((long long)zk * pstr + (long long)zb * sCz)
                                 : ((long long)zb * sCz);

    int tid = threadIdx.x, lane = tid & 31, warp = tid >> 5;
    int wk = warp >> 2;
    int wm = (warp >> 1) & 1, wn = warp & 1;
    int m0 = blockIdx.y * 64, n0 = blockIdx.x * 64;

    int lr = tid >> 2;
    int lq = (tid & 3) * 8;
    int lo = lr * 80 + (tid & 3) * 16;

    const __nv_bfloat16* pAh = Ah_ + (long long)(m0 + lr) * lda + lq;
    const __nv_bfloat16* pAl = Al_ + (long long)(m0 + lr) * lda + lq;
    const __nv_bfloat16* pWh = Wh_ + (long long)(n0 + lr) * ldw + lq;
    const __nv_bfloat16* pWl = Wl_ + (long long)(n0 + lr) * ldw + lq;

    uint32_t smb = smem_u32(smraw);

    auto issue = [&](uint32_t so, int k0) {
        CPA16(smb + so + lo,          (const char*)(pAh + k0));
        CPA16(smb + so + 5120  + lo,  (const char*)(pAl + k0));
        CPA16(smb + so + 10240 + lo,  (const char*)(pWh + k0));
        CPA16(smb + so + 15360 + lo,  (const char*)(pWl + k0));
        CP_COMMIT();
    };

    float acc[2][4][4];
#pragma unroll
    for (int s = 0; s < 2; s++)
#pragma unroll
        for (int nb = 0; nb < 4; nb++)
#pragma unroll
            for (int i = 0; i < 4; i++) acc[s][nb][i] = 0.f;

    uint32_t aBase = smb + (uint32_t)((wm * 32 + (lane & 15)) * 80
                   + ((lane >> 4) & 1) * 16 + wk * 32);
    uint32_t bBase = smb + 10240u +
        (uint32_t)((wn * 32 + ((lane >> 4) & 1) * 8 + (lane & 7)) * 80
                   + ((lane >> 3) & 1) * 16 + wk * 32);

    int NT = Kslice / 32;
    issue(0, 0);
    if (NT > 1) issue(20480, 32);

    for (int t = 0; t < NT; t++) {
        if (t + 1 < NT) { CP_WAIT1(); } else { CP_WAIT0(); }
        __syncthreads();

        uint32_t bufo = (uint32_t)(t & 1) * 20480u;
        uint32_t ah[2][4], alr[2][4];
#pragma unroll
        for (int s = 0; s < 2; s++) {
            uint32_t ad = aBase + bufo + (uint32_t)(s * 1280);
            ldsm4(ah[s][0], ah[s][1], ah[s][2], ah[s][3], ad);
            ldsm4(alr[s][0], alr[s][1], alr[s][2], alr[s][3], ad + 5120u);
        }
        uint32_t bh[4][2], blr[4][2];
#pragma unroll
        for (int p = 0; p < 2; p++) {
            uint32_t bd = bBase + bufo + (uint32_t)(p * 1280);
            ldsm4(bh[2*p][0], bh[2*p][1], bh[2*p+1][0], bh[2*p+1][1], bd);
            ldsm4(blr[2*p][0], blr[2*p][1], blr[2*p+1][0], blr[2*p+1][1], bd + 5120u);
        }
#pragma unroll
        for (int s = 0; s < 2; s++)
#pragma unroll
            for (int nb = 0; nb < 4; nb++)
                mma_bf16(acc[s][nb], ah[s], bh[nb][0], bh[nb][1]);
#pragma unroll
        for (int s = 0; s < 2; s++)
#pragma unroll
            for (int nb = 0; nb < 4; nb++)
                mma_bf16(acc[s][nb], ah[s], blr[nb][0], blr[nb][1]);
#pragma unroll
        for (int s = 0; s < 2; s++)
#pragma unroll
            for (int nb = 0; nb < 4; nb++)
                mma_bf16(acc[s][nb], alr[s], bh[nb][0], bh[nb][1]);

        __syncthreads();
        if (t + 2 < NT) issue((uint32_t)(t & 1) * 20480u, (t + 2) * 32);
    }

    int erow = lane >> 2;
    int ecol = (lane & 3) * 2;
    float* red = (float*)smraw;
    if (wk == 1) {
#pragma unroll
        for (int s = 0; s < 2; s++) {
            int r0 = wm * 32 + s * 16 + erow;
#pragma unroll
            for (int nb = 0; nb < 4; nb++) {
                int col = wn * 32 + nb * 8 + ecol;
                *(float2*)(red + r0 * 68 + col)       = make_float2(acc[s][nb][0], acc[s][nb][1]);
                *(float2*)(red + (r0 + 8) * 68 + col) = make_float2(acc[s][nb][2], acc[s][nb][3]);
            }
        }
    }
    __syncthreads();
    if (wk != 0) return;

#pragma unroll
    for (int s = 0; s < 2; s++) {
        int rl = wm * 32 + s * 16 + erow;
        int r0 = m0 + rl;
#pragma unroll
        for (int nb = 0; nb < 4; nb++) {
            int cl = wn * 32 + nb * 8 + ecol;
            int col = n0 + cl;
            float2 o0 = *(const float2*)(red + rl * 68 + cl);
            float2 o1 = *(const float2*)(red + (rl + 8) * 68 + cl);
            float v00 = acc[s][nb][0] + o0.x, v01 = acc[s][nb][1] + o0.y;
            float v10 = acc[s][nb][2] + o1.x, v11 = acc[s][nb][3] + o1.y;
            if (MODE == 2) {
                *(float2*)(Cf + coff + (long long)r0 * ldc + col)       = make_float2(v00, v01);
                *(float2*)(Cf + coff + (long long)(r0 + 8) * ldc + col) = make_float2(v10, v11);
            } else {
                float b0 = bp ? bp[col] : 0.f;
                float b1 = bp ? bp[col + 1] : 0.f;
                *(float2*)(Cf + coff + (long long)r0 * ldc + col)
                    = make_float2(alpha * (v00 + b0), alpha * (v01 + b1));
                *(float2*)(Cf + coff + (long long)(r0 + 8) * ldc + col)
                    = make_float2(alpha * (v10 + b0), alpha * (v11 + b1));
            }
        }
    }
}

// ---------------------------------------------------------------------------
// Fused attention (R10 version — online softmax, col-sliced xa)
// ---------------------------------------------------------------------------
__global__ __launch_bounds__(256)
void attn_kernel(const float* __restrict__ x,
                 const float* __restrict__ qk,
                 const int*   __restrict__ seg,
                 __nv_bfloat16* __restrict__ xah,
                 __nv_bfloat16* __restrict__ xal)
{
    __shared__ float qks[16 * 260];
    __shared__ float xs [16 * 260];
    __shared__ float sw [16 * 20];
    __shared__ float sscale[16];
    __shared__ float sD[16];

    int b = blockIdx.x;
    int t = threadIdx.x;
    int s0 = seg[b];
    int len = seg[b + 1] - s0;
    if (len > MAXLEN) len = MAXLEN;

    const float4* qk4 = (const float4*)(qk + (long long)b * (NHEAD * D_DRUG));
#pragma unroll
    for (int r = 0; r < 4; r++) {
        int idx = t + r * 256;
        int h = idx >> 6, jj = idx & 63;
        *(float4*)&qks[h * 260 + jj * 4] = qk4[idx];
    }
    __syncthreads();

    int h  = t >> 4;
    int mm = t & 15;
    int w2 = t >> 5, lane = t & 31;
    int hx = lane >> 1, cx = lane & 1;
    int j0x = w2 * 32 + cx * 16;

    float M = -3.0e38f, D = 0.f;
    F2U acc[8];
#pragma unroll
    for (int i = 0; i < 8; i++) acc[i].f = make_float2(0.f, 0.f);

    for (int m0 = 0; m0 < len; m0 += 16) {
        int nm = len - m0; if (nm > 16) nm = 16;
#pragma unroll
        for (int r = 0; r < 4; r++) {
            int idx = t + r * 256;
            int row = idx >> 6, jj = idx & 63;
            if (row < nm)
                *(float4*)&xs[row * 260 + jj * 4] =
                    *(const float4*)(x + (long long)(s0 + m0 + row) * D_DRUG + jj * 4);
        }
        __syncthreads();

        float myscore = -3.0e38f;
        if (mm < nm) {
            const float* qp = &qks[h * 260];
            const float* xp = &xs[mm * 260];
            F2U a0, a1;
            a0.f = make_float2(0.f, 0.f);
            a1.f = make_float2(0.f, 0.f);
#pragma unroll
            for (int j = 0; j < 256; j += 8) {
                float4 q0 = *(const float4*)(qp + j);
                float4 x0 = *(const float4*)(xp + j);
                float4 q1 = *(const float4*)(qp + j + 4);
                float4 x1 = *(const float4*)(xp + j + 4);
                F2U aa, bb;
                aa.f = make_float2(q0.x, q0.y); bb.f = make_float2(x0.x, x0.y); fma2(a0, aa, bb);
                aa.f = make_float2(q0.z, q0.w); bb.f = make_float2(x0.z, x0.w); fma2(a1, aa, bb);
                aa.f = make_float2(q1.x, q1.y); bb.f = make_float2(x1.x, x1.y); fma2(a0, aa, bb);
                aa.f = make_float2(q1.z, q1.w); bb.f = make_float2(x1.z, x1.w); fma2(a1, aa, bb);
            }
            myscore = a0.f.x + a0.f.y + a1.f.x + a1.f.y;
        }

        float tmax = myscore;
#pragma unroll
        for (int o = 1; o < 16; o <<= 1)
            tmax = fmaxf(tmax, __shfl_xor_sync(0xffffffffu, tmax, o));
        float newM = fmaxf(M, tmax);
        float scale = __expf(M - newM);
        float w = (mm < nm) ? __expf(myscore - newM) : 0.f;
        float ws = w;
#pragma unroll
        for (int o = 1; o < 16; o <<= 1)
            ws += __shfl_xor_sync(0xffffffffu, ws, o);
        D = D * scale + ws;
        M = newM;
        sw[h * 20 + mm] = w;
        if (mm == 0) sscale[h] = scale;
        __syncthreads();

        float sc2 = sscale[hx];
#pragma unroll
        for (int i = 0; i < 8; i++) { acc[i].f.x *= sc2; acc[i].f.y *= sc2; }
        const float* swr = &sw[hx * 20];
        for (int i = 0; i < nm; i++) {
            float a = swr[i];
            F2U ad; ad.f = make_float2(a, a);
            const float* xr = &xs[i * 260 + j0x];
#pragma unroll
            for (int r = 0; r < 4; r++) {
                float4 v = *(const float4*)(xr + r * 4);
                F2U b0, b1;
                b0.f = make_float2(v.x, v.y);
                b1.f = make_float2(v.z, v.w);
                fma2(acc[2 * r], ad, b0);
                fma2(acc[2 * r + 1], ad, b1);
            }
        }
        __syncthreads();
    }

    if (mm == 0) sD[h] = D;
    __syncthreads();

    float Df = sD[hx];
    float inv = (Df > 0.f) ? (1.0f / Df) : 0.f;
    long long base = (long long)b * (NHEAD * D_DRUG) + hx * D_DRUG + j0x;
#pragma unroll
    for (int i = 0; i < 8; i++) {
        float va = acc[i].f.x * inv, vb = acc[i].f.y * inv;
        __nv_bfloat16 ha = __float2bfloat16(va), hb = __float2bfloat16(vb);
        uint32_t ph = (uint32_t)__bfloat16_as_ushort(ha)
                    | ((uint32_t)__bfloat16_as_ushort(hb) << 16);
        uint32_t pl = pack_bf16(va - __bfloat162float(ha), vb - __bfloat162float(hb));
        *(uint32_t*)(xah + base + i * 2) = ph;
        *(uint32_t*)(xal + base + i * 2) = pl;
    }
}

// ---------------------------------------------------------------------------
// Launch
// ---------------------------------------------------------------------------
extern "C" void kernel_launch(void* const* d_in, const int* in_sizes, int n_in,
                              void* d_out, int out_size)
{
    const float* x_nodes = (const float*)d_in[0];
    const float* cell    = (const float*)d_in[1];
    const float* Wq      = (const float*)d_in[2];
    const float* bq      = (const float*)d_in[3];
    const float* Wk      = (const float*)d_in[4];
    /* bk cancels in softmax */
    const float* Wv      = (const float*)d_in[6];
    const float* bv      = (const float*)d_in[7];
    const float* Wo      = (const float*)d_in[8];
    const float* bo      = (const float*)d_in[9];
    const float* Wc      = (const float*)d_in[10];
    const float* bc      = (const float*)d_in[11];
    const void*  guide   = d_in[12];
    float*       out     = (float*)d_out;

    int N = in_sizes[12];

    float *qkp, *part; int* seg;
    __nv_bfloat16 *a0h, *a0l, *a1h, *a1l, *xah, *xal;
    __nv_bfloat16 *wch, *wcl, *wqh, *wql, *woh, *wol, *wvh, *wvl, *wkth, *wktl;
    cudaGetSymbolAddress((void**)&qkp,  g_qk);
    cudaGetSymbolAddress((void**)&part, g_part);
    cudaGetSymbolAddress((void**)&seg,  g_seg);
    cudaGetSymbolAddress((void**)&a0h,  g_a0h);
    cudaGetSymbolAddress((void**)&a0l,  g_a0l);
    cudaGetSymbolAddress((void**)&a1h,  g_a1h);
    cudaGetSymbolAddress((void**)&a1l,  g_a1l);
    cudaGetSymbolAddress((void**)&xah,  g_xah);
    cudaGetSymbolAddress((void**)&xal,  g_xal);
    cudaGetSymbolAddress((void**)&wch,  g_wch);
    cudaGetSymbolAddress((void**)&wcl,  g_wcl);
    cudaGetSymbolAddress((void**)&wqh,  g_wqh);
    cudaGetSymbolAddress((void**)&wql,  g_wql);
    cudaGetSymbolAddress((void**)&woh,  g_woh);
    cudaGetSymbolAddress((void**)&wol,  g_wol);
    cudaGetSymbolAddress((void**)&wvh,  g_wvh);
    cudaGetSymbolAddress((void**)&wvl,  g_wvl);
    cudaGetSymbolAddress((void**)&wkth, g_wkth);
    cudaGetSymbolAddress((void**)&wktl, g_wktl);

    const long long PSTR = (long long)BATCH * EMB;

    // 1: prep-A (only G1's inputs: Wc + cell splits)
    prepA_kernel<<<1536, 256>>>((const float4*)Wc, (const float4*)cell,
                                (uint2*)wch, (uint2*)wcl, (uint2*)a0h, (uint2*)a0l);

    // 2: G1 (split-K4) fused with prep-B (Wq/Wo/Wv splits, WkT, seg, copy)
    g1_fused<<<3587, 256>>>(a0h, a0l, wch, wcl, part, PSTR,
                            (const float4*)Wq, (const float4*)Wo, (const float4*)Wv,
                            (const float4*)cell, Wk, guide, N,
                            (uint2*)wqh, (uint2*)wql, (uint2*)woh, (uint2*)wol,
                            (uint2*)wvh, (uint2*)wvl, wkth, wktl, seg, (float4*)out);

    // 3: reduce +bc -> a1 hi/lo
    reduce_k<0, 4><<<512, 256>>>((const float4*)part, bc, nullptr, a1h, a1l, EMB, 1.0f);

    // 4 (profiled slot): G2 q = cq @ Wq^T (split-K4)
    mma_gemm3x<2><<<dim3(16, 8, 4), 256>>>(
        a1h, a1l, EMB, 0, wqh, wql, EMB, 0, nullptr, 0,
        part, EMB, 0, 1.0f, 256, 4, PSTR);
    // 5: reduce (+bq)*0.125 -> a0 hi/lo
    reduce_k<0, 4><<<512, 256>>>((const float4*)part, bq, nullptr, a0h, a0l, EMB, 0.125f);

    // 6: qk = q @ WkT per head
    mma_gemm3x<1><<<dim3(4, 8, 16), 256>>>(
        a0h, a0l, EMB, HDIM, wkth, wktl, HDIM, (long long)D_DRUG * HDIM, nullptr, 0,
        qkp, NHEAD * D_DRUG, D_DRUG, 1.0f, HDIM, 1, 0);

    // 7: attention
    attn_kernel<<<512, 256>>>(x_nodes, qkp, seg, xah, xal);

    // 8: vv per head (split-K4)
    mma_gemm3x<2><<<dim3(1, 8, 64), 256>>>(
        xah, xal, NHEAD * D_DRUG, D_DRUG, wvh, wvl, D_DRUG, (long long)HDIM * D_DRUG,
        nullptr, 0, part, EMB, HDIM, 1.0f, 64, 4, PSTR);
    // 9: reduce +bv -> a1 hi/lo
    reduce_k<0, 4><<<512, 256>>>((const float4*)part, bv, nullptr, a1h, a1l, EMB, 1.0f);

    // 10: G3 out = op @ Wo^T (split-K4)
    mma_gemm3x<2><<<dim3(16, 8, 4), 256>>>(
        a1h, a1l, EMB, 0, woh, wol, EMB, 0, nullptr, 0,
        part, EMB, 0, 1.0f, 256, 4, PSTR);
    // 11: reduce +bo -> fp32 strided into out
    reduce_k<1, 4><<<512, 256>>>((const float4*)part, bo, out, nullptr, nullptr,
                                 EMB + D_CELL, 1.0f);

    (void)n_in; (void)out_size;
}

// round 16
// speedup vs baseline: 1.1436x; 1.0399x over previous
#include <cuda_runtime.h>
#include <cuda_bf16.h>
#include <cstdint>

// ---------------------------------------------------------------------------
// Problem constants
// ---------------------------------------------------------------------------
#define BATCH   512
#define MAXLEN  128
#define D_DRUG  256
#define D_CELL  1024
#define NHEAD   16
#define HDIM    64
#define EMB     1024   // NHEAD*HDIM

// ---------------------------------------------------------------------------
// Scratch (device globals)
// ---------------------------------------------------------------------------
__device__ float g_qk  [BATCH * NHEAD * D_DRUG];
__device__ float g_part[4 * BATCH * EMB];
__device__ int   g_seg [BATCH + 1];

__device__ __nv_bfloat16 g_a0h[BATCH * EMB],   g_a0l[BATCH * EMB];
__device__ __nv_bfloat16 g_a1h[BATCH * EMB],   g_a1l[BATCH * EMB];
__device__ __nv_bfloat16 g_xah[BATCH * NHEAD * D_DRUG], g_xal[BATCH * NHEAD * D_DRUG];
__device__ __nv_bfloat16 g_wch[EMB * D_CELL],  g_wcl[EMB * D_CELL];
__device__ __nv_bfloat16 g_wqh[EMB * EMB],     g_wql[EMB * EMB];
__device__ __nv_bfloat16 g_woh[EMB * EMB],     g_wol[EMB * EMB];
__device__ __nv_bfloat16 g_wvh[EMB * D_DRUG],  g_wvl[EMB * D_DRUG];
__device__ __nv_bfloat16 g_wkth[NHEAD * D_DRUG * HDIM], g_wktl[NHEAD * D_DRUG * HDIM];

// ---------------------------------------------------------------------------
// Helpers
// ---------------------------------------------------------------------------
union F2U { float2 f; unsigned long long u; };
__device__ __forceinline__ void fma2(F2U &c, F2U a, F2U b) {
    asm("fma.rn.f32x2 %0, %1, %2, %0;" : "+l"(c.u) : "l"(a.u), "l"(b.u));
}

__device__ __forceinline__ uint32_t smem_u32(const void* p) {
    uint32_t a;
    asm("{ .reg .u64 t; cvta.to.shared.u64 t, %1; cvt.u32.u64 %0, t; }" : "=r"(a) : "l"(p));
    return a;
}

__device__ __forceinline__ void ldsm4(uint32_t &r0, uint32_t &r1, uint32_t &r2, uint32_t &r3,
                                      uint32_t a) {
    asm volatile("ldmatrix.sync.aligned.m8n8.x4.shared.b16 {%0,%1,%2,%3}, [%4];"
        : "=r"(r0), "=r"(r1), "=r"(r2), "=r"(r3) : "r"(a));
}

__device__ __forceinline__ void mma_bf16(float c[4], const uint32_t a[4],
                                         uint32_t b0, uint32_t b1) {
    asm volatile("mma.sync.aligned.m16n8k16.row.col.f32.bf16.bf16.f32 "
        "{%0,%1,%2,%3}, {%4,%5,%6,%7}, {%8,%9}, {%0,%1,%2,%3};"
        : "+f"(c[0]), "+f"(c[1]), "+f"(c[2]), "+f"(c[3])
        : "r"(a[0]), "r"(a[1]), "r"(a[2]), "r"(a[3]), "r"(b0), "r"(b1));
}

__device__ __forceinline__ uint32_t pack_bf16(float a, float b) {
    return (uint32_t)__bfloat16_as_ushort(__float2bfloat16(a))
         | ((uint32_t)__bfloat16_as_ushort(__float2bfloat16(b)) << 16);
}

#define CPA16(sm, gp) asm volatile("cp.async.cg.shared.global [%0], [%1], 16;" :: "r"(sm), "l"(gp))
#define CP_COMMIT()   asm volatile("cp.async.commit_group;" ::: "memory")
#define CP_WAIT0()    asm volatile("cp.async.wait_group 0;" ::: "memory")
#define CP_WAIT1()    asm volatile("cp.async.wait_group 1;" ::: "memory")

__device__ __forceinline__ void split4(const float4* s, uint2* hi, uint2* lo, int i)
{
    float4 v = s[i];
    __nv_bfloat16 h0 = __float2bfloat16(v.x), h1 = __float2bfloat16(v.y);
    __nv_bfloat16 h2 = __float2bfloat16(v.z), h3 = __float2bfloat16(v.w);
    uint2 H, L;
    H.x = (uint32_t)__bfloat16_as_ushort(h0) | ((uint32_t)__bfloat16_as_ushort(h1) << 16);
    H.y = (uint32_t)__bfloat16_as_ushort(h2) | ((uint32_t)__bfloat16_as_ushort(h3) << 16);
    L.x = pack_bf16(v.x - __bfloat162float(h0), v.y - __bfloat162float(h1));
    L.y = pack_bf16(v.z - __bfloat162float(h2), v.w - __bfloat162float(h3));
    hi[i] = H; lo[i] = L;
}

// ---------------------------------------------------------------------------
// prep-A: only what G1 needs — Wc split + cell split
// ---------------------------------------------------------------------------
__global__ __launch_bounds__(256)
void prepA_kernel(const float4* Wc, const float4* cell,
                  uint2* wch, uint2* wcl, uint2* ah, uint2* al)
{
    int i = blockIdx.x * 256 + threadIdx.x;
    if (i < 262144)       split4(Wc, wch, wcl, i);
    else if (i < 393216)  split4(cell, ah, al, i - 262144);
}

// ---------------------------------------------------------------------------
// G1 GEMM (split-K2, k-group kernel) FUSED with prep-B as extra blocks.
// blocks [0,256):    GEMM  part[zk] slices (16 n-tiles x 8 m-tiles x 2 zk)
// blocks [256,3331): prep-B (Wq/Wo/Wv splits, WkT, seg, copy_cell)
// ---------------------------------------------------------------------------
__global__ __launch_bounds__(256)
void g1_fused(const __nv_bfloat16* __restrict__ Ah, const __nv_bfloat16* __restrict__ Al,
              const __nv_bfloat16* __restrict__ Wh, const __nv_bfloat16* __restrict__ Wl,
              float* __restrict__ part, long long pstr,
              const float4* Wq, const float4* Wo, const float4* Wv, const float4* cell,
              const float* Wk, const void* guide, int n,
              uint2* wqh, uint2* wql, uint2* woh, uint2* wol,
              uint2* wvh, uint2* wvl,
              __nv_bfloat16* wkth, __nv_bfloat16* wktl,
              int* seg, float4* outp)
{
    __shared__ __align__(16) char smraw[40960];
    int gx = blockIdx.x, tid = threadIdx.x;

    if (gx >= 256) {
        // ---- prep-B ----
        int pb = gx - 256;
        if (pb < 2048) {
            int i = pb * 256 + tid;
            if (i < 262144) split4(Wq, wqh, wql, i);
            else            split4(Wo, woh, wol, i - 262144);
        } else if (pb < 2304) {
            int i = (pb - 2048) * 256 + tid;
            split4(Wv, wvh, wvl, i);
        } else if (pb < 2560) {
            float (*tile)[33] = (float (*)[33])smraw;
            int b2 = pb - 2304;
            int nt = b2 & 7, dt = (b2 >> 3) & 1, h = b2 >> 4;
            int tx = tid & 31, ty = tid >> 5;
#pragma unroll
            for (int r = ty; r < 32; r += 8)
                tile[r][tx] = Wk[(long long)(h * 64 + dt * 32 + r) * D_DRUG + nt * 32 + tx];
            __syncthreads();
#pragma unroll
            for (int r = ty; r < 32; r += 8) {
                float v = tile[tx][r];
                __nv_bfloat16 hh = __float2bfloat16(v);
                long long o = (long long)h * (D_DRUG * HDIM)
                            + (long long)(nt * 32 + r) * HDIM + dt * 32 + tx;
                wkth[o] = hh;
                wktl[o] = __float2bfloat16(v - __bfloat162float(hh));
            }
        } else if (pb < 2563) {
            int g = (pb - 2560) * 256 + tid;
            if (g <= BATCH) {
                const unsigned long long* g64 = (const unsigned long long*)guide;
                const int*                g32 = (const int*)guide;
                bool is64 = (g64[(n >> 1) - 1] <= 511ull);
                int lo2 = 0, hi2 = n;
                while (lo2 < hi2) {
                    int mid = (lo2 + hi2) >> 1;
                    long long v = is64 ? (long long)g64[mid] : (long long)g32[mid];
                    if (v < (long long)g) lo2 = mid + 1; else hi2 = mid;
                }
                seg[g] = lo2;
            }
        } else {
            int i = (pb - 2563) * 256 + tid;
            if (i < BATCH * (D_CELL / 4)) {
                int b = i >> 8, j = i & 255;
                outp[b * ((EMB + D_CELL) / 4) + (EMB / 4) + j] = cell[i];
            }
        }
        return;
    }

    // ---- G1 GEMM CTA: x = n-tile (16), y = m-tile (8), zk (2), Kslice 512 ----
    int xg = gx & 15, yg = (gx >> 4) & 7, zk = gx >> 7;
    const int Kslice = 512;
    const __nv_bfloat16* Ah_ = Ah + (long long)zk * Kslice;
    const __nv_bfloat16* Al_ = Al + (long long)zk * Kslice;
    const __nv_bfloat16* Wh_ = Wh + (long long)zk * Kslice;
    const __nv_bfloat16* Wl_ = Wl + (long long)zk * Kslice;
    long long coff = (long long)zk * pstr;

    int lane = tid & 31, warp = tid >> 5;
    int wk = warp >> 2;
    int wm = (warp >> 1) & 1, wn = warp & 1;
    int m0 = yg * 64, n0 = xg * 64;

    int lr = tid >> 2;
    int lq = (tid & 3) * 8;
    int lo = lr * 80 + (tid & 3) * 16;

    const __nv_bfloat16* pAh = Ah_ + (long long)(m0 + lr) * D_CELL + lq;
    const __nv_bfloat16* pAl = Al_ + (long long)(m0 + lr) * D_CELL + lq;
    const __nv_bfloat16* pWh = Wh_ + (long long)(n0 + lr) * D_CELL + lq;
    const __nv_bfloat16* pWl = Wl_ + (long long)(n0 + lr) * D_CELL + lq;

    uint32_t smb = smem_u32(smraw);

    auto issue = [&](uint32_t so, int k0) {
        CPA16(smb + so + lo,          (const char*)(pAh + k0));
        CPA16(smb + so + 5120  + lo,  (const char*)(pAl + k0));
        CPA16(smb + so + 10240 + lo,  (const char*)(pWh + k0));
        CPA16(smb + so + 15360 + lo,  (const char*)(pWl + k0));
        CP_COMMIT();
    };

    float acc[2][4][4];
#pragma unroll
    for (int s = 0; s < 2; s++)
#pragma unroll
        for (int nb = 0; nb < 4; nb++)
#pragma unroll
            for (int i = 0; i < 4; i++) acc[s][nb][i] = 0.f;

    uint32_t aBase = smb + (uint32_t)((wm * 32 + (lane & 15)) * 80
                   + ((lane >> 4) & 1) * 16 + wk * 32);
    uint32_t bBase = smb + 10240u +
        (uint32_t)((wn * 32 + ((lane >> 4) & 1) * 8 + (lane & 7)) * 80
                   + ((lane >> 3) & 1) * 16 + wk * 32);

    const int NT = Kslice / 32;
    issue(0, 0);
    issue(20480, 32);

    for (int t = 0; t < NT; t++) {
        if (t + 1 < NT) { CP_WAIT1(); } else { CP_WAIT0(); }
        __syncthreads();

        uint32_t bufo = (uint32_t)(t & 1) * 20480u;
        uint32_t ah[2][4], alr[2][4];
#pragma unroll
        for (int s = 0; s < 2; s++) {
            uint32_t ad = aBase + bufo + (uint32_t)(s * 1280);
            ldsm4(ah[s][0], ah[s][1], ah[s][2], ah[s][3], ad);
            ldsm4(alr[s][0], alr[s][1], alr[s][2], alr[s][3], ad + 5120u);
        }
        uint32_t bh[4][2], blr[4][2];
#pragma unroll
        for (int p = 0; p < 2; p++) {
            uint32_t bd = bBase + bufo + (uint32_t)(p * 1280);
            ldsm4(bh[2*p][0], bh[2*p][1], bh[2*p+1][0], bh[2*p+1][1], bd);
            ldsm4(blr[2*p][0], blr[2*p][1], blr[2*p+1][0], blr[2*p+1][1], bd + 5120u);
        }
#pragma unroll
        for (int s = 0; s < 2; s++)
#pragma unroll
            for (int nb = 0; nb < 4; nb++)
                mma_bf16(acc[s][nb], ah[s], bh[nb][0], bh[nb][1]);
#pragma unroll
        for (int s = 0; s < 2; s++)
#pragma unroll
            for (int nb = 0; nb < 4; nb++)
                mma_bf16(acc[s][nb], ah[s], blr[nb][0], blr[nb][1]);
#pragma unroll
        for (int s = 0; s < 2; s++)
#pragma unroll
            for (int nb = 0; nb < 4; nb++)
                mma_bf16(acc[s][nb], alr[s], bh[nb][0], bh[nb][1]);

        __syncthreads();
        if (t + 2 < NT) issue((uint32_t)(t & 1) * 20480u, (t + 2) * 32);
    }

    int erow = lane >> 2;
    int ecol = (lane & 3) * 2;
    float* red = (float*)smraw;
    if (wk == 1) {
#pragma unroll
        for (int s = 0; s < 2; s++) {
            int r0 = wm * 32 + s * 16 + erow;
#pragma unroll
            for (int nb = 0; nb < 4; nb++) {
                int col = wn * 32 + nb * 8 + ecol;
                *(float2*)(red + r0 * 68 + col)       = make_float2(acc[s][nb][0], acc[s][nb][1]);
                *(float2*)(red + (r0 + 8) * 68 + col) = make_float2(acc[s][nb][2], acc[s][nb][3]);
            }
        }
    }
    __syncthreads();
    if (wk != 0) return;

#pragma unroll
    for (int s = 0; s < 2; s++) {
        int rl = wm * 32 + s * 16 + erow;
        int r0 = m0 + rl;
#pragma unroll
        for (int nb = 0; nb < 4; nb++) {
            int cl = wn * 32 + nb * 8 + ecol;
            int col = n0 + cl;
            float2 o0 = *(const float2*)(red + rl * 68 + cl);
            float2 o1 = *(const float2*)(red + (rl + 8) * 68 + cl);
            *(float2*)(part + coff + (long long)r0 * EMB + col)
                = make_float2(acc[s][nb][0] + o0.x, acc[s][nb][1] + o0.y);
            *(float2*)(part + coff + (long long)(r0 + 8) * EMB + col)
                = make_float2(acc[s][nb][2] + o1.x, acc[s][nb][3] + o1.y);
        }
    }
}

// ---------------------------------------------------------------------------
// Split-K reduce, NS slices (MLP=NS)
// ---------------------------------------------------------------------------
template <int MODE, int NS>
__global__ __launch_bounds__(256)
void reduce_k(const float4* __restrict__ part, const float* __restrict__ bias,
              float* __restrict__ outf, __nv_bfloat16* __restrict__ oh,
              __nv_bfloat16* __restrict__ ol, int ldc, float alpha)
{
    int i = blockIdx.x * 256 + threadIdx.x;
    if (i >= BATCH * (EMB / 4)) return;
    int b = i >> 8, j = i & 255;
    float4 p[NS];
#pragma unroll
    for (int k = 0; k < NS; k++) p[k] = part[k * (BATCH * EMB / 4) + i];
    float4 s = p[0];
#pragma unroll
    for (int k = 1; k < NS; k++) { s.x += p[k].x; s.y += p[k].y; s.z += p[k].z; s.w += p[k].w; }
    int col = j * 4;
    float4 bb = *(const float4*)(bias + col);
    float vx = alpha * (s.x + bb.x), vy = alpha * (s.y + bb.y);
    float vz = alpha * (s.z + bb.z), vw = alpha * (s.w + bb.w);
    if (MODE == 1) {
        *(float4*)(outf + (long long)b * ldc + col) = make_float4(vx, vy, vz, vw);
    } else {
        __nv_bfloat16 h0 = __float2bfloat16(vx), h1 = __float2bfloat16(vy);
        __nv_bfloat16 h2 = __float2bfloat16(vz), h3 = __float2bfloat16(vw);
        uint2 H, L;
        H.x = (uint32_t)__bfloat16_as_ushort(h0) | ((uint32_t)__bfloat16_as_ushort(h1) << 16);
        H.y = (uint32_t)__bfloat16_as_ushort(h2) | ((uint32_t)__bfloat16_as_ushort(h3) << 16);
        L.x = pack_bf16(vx - __bfloat162float(h0), vy - __bfloat162float(h1));
        L.y = pack_bf16(vz - __bfloat162float(h2), vw - __bfloat162float(h3));
        *(uint2*)(oh + (long long)b * ldc + col) = H;
        *(uint2*)(ol + (long long)b * ldc + col) = L;
    }
}

// ---------------------------------------------------------------------------
// bf16x3 MMA GEMM — R14 k-group kernel (measured best class)
// ---------------------------------------------------------------------------
template <int MODE>
__global__ __launch_bounds__(256)
void mma_gemm3x(const __nv_bfloat16* __restrict__ Ah, const __nv_bfloat16* __restrict__ Al,
                int lda, long long sAz,
                const __nv_bfloat16* __restrict__ Wh, const __nv_bfloat16* __restrict__ Wl,
                int ldw, long long sWz,
                const float* __restrict__ bias, long long sbz,
                float* __restrict__ Cf,
                int ldc, long long sCz, float alpha, int Kslice, int nks, long long pstr)
{
    __shared__ __align__(16) char smraw[40960];

    int zb = blockIdx.z / nks, zk = blockIdx.z % nks;
    const __nv_bfloat16* Ah_ = Ah + (long long)zb * sAz + (long long)zk * Kslice;
    const __nv_bfloat16* Al_ = Al + (long long)zb * sAz + (long long)zk * Kslice;
    const __nv_bfloat16* Wh_ = Wh + (long long)zb * sWz + (long long)zk * Kslice;
    const __nv_bfloat16* Wl_ = Wl + (long long)zb * sWz + (long long)zk * Kslice;
    const float* bp = bias ? bias + (long long)zb * sbz : nullptr;
    long long coff = (MODE == 2) ? ((long long)zk * pstr + (long long)zb * sCz)
                                 : ((long long)zb * sCz);

    int tid = threadIdx.x, lane = tid & 31, warp = tid >> 5;
    int wk = warp >> 2;
    int wm = (warp >> 1) & 1, wn = warp & 1;
    int m0 = blockIdx.y * 64, n0 = blockIdx.x * 64;

    int lr = tid >> 2;
    int lq = (tid & 3) * 8;
    int lo = lr * 80 + (tid & 3) * 16;

    const __nv_bfloat16* pAh = Ah_ + (long long)(m0 + lr) * lda + lq;
    const __nv_bfloat16* pAl = Al_ + (long long)(m0 + lr) * lda + lq;
    const __nv_bfloat16* pWh = Wh_ + (long long)(n0 + lr) * ldw + lq;
    const __nv_bfloat16* pWl = Wl_ + (long long)(n0 + lr) * ldw + lq;

    uint32_t smb = smem_u32(smraw);

    auto issue = [&](uint32_t so, int k0) {
        CPA16(smb + so + lo,          (const char*)(pAh + k0));
        CPA16(smb + so + 5120  + lo,  (const char*)(pAl + k0));
        CPA16(smb + so + 10240 + lo,  (const char*)(pWh + k0));
        CPA16(smb + so + 15360 + lo,  (const char*)(pWl + k0));
        CP_COMMIT();
    };

    float acc[2][4][4];
#pragma unroll
    for (int s = 0; s < 2; s++)
#pragma unroll
        for (int nb = 0; nb < 4; nb++)
#pragma unroll
            for (int i = 0; i < 4; i++) acc[s][nb][i] = 0.f;

    uint32_t aBase = smb + (uint32_t)((wm * 32 + (lane & 15)) * 80
                   + ((lane >> 4) & 1) * 16 + wk * 32);
    uint32_t bBase = smb + 10240u +
        (uint32_t)((wn * 32 + ((lane >> 4) & 1) * 8 + (lane & 7)) * 80
                   + ((lane >> 3) & 1) * 16 + wk * 32);

    int NT = Kslice / 32;
    issue(0, 0);
    if (NT > 1) issue(20480, 32);

    for (int t = 0; t < NT; t++) {
        if (t + 1 < NT) { CP_WAIT1(); } else { CP_WAIT0(); }
        __syncthreads();

        uint32_t bufo = (uint32_t)(t & 1) * 20480u;
        uint32_t ah[2][4], alr[2][4];
#pragma unroll
        for (int s = 0; s < 2; s++) {
            uint32_t ad = aBase + bufo + (uint32_t)(s * 1280);
            ldsm4(ah[s][0], ah[s][1], ah[s][2], ah[s][3], ad);
            ldsm4(alr[s][0], alr[s][1], alr[s][2], alr[s][3], ad + 5120u);
        }
        uint32_t bh[4][2], blr[4][2];
#pragma unroll
        for (int p = 0; p < 2; p++) {
            uint32_t bd = bBase + bufo + (uint32_t)(p * 1280);
            ldsm4(bh[2*p][0], bh[2*p][1], bh[2*p+1][0], bh[2*p+1][1], bd);
            ldsm4(blr[2*p][0], blr[2*p][1], blr[2*p+1][0], blr[2*p+1][1], bd + 5120u);
        }
#pragma unroll
        for (int s = 0; s < 2; s++)
#pragma unroll
            for (int nb = 0; nb < 4; nb++)
                mma_bf16(acc[s][nb], ah[s], bh[nb][0], bh[nb][1]);
#pragma unroll
        for (int s = 0; s < 2; s++)
#pragma unroll
            for (int nb = 0; nb < 4; nb++)
                mma_bf16(acc[s][nb], ah[s], blr[nb][0], blr[nb][1]);
#pragma unroll
        for (int s = 0; s < 2; s++)
#pragma unroll
            for (int nb = 0; nb < 4; nb++)
                mma_bf16(acc[s][nb], alr[s], bh[nb][0], bh[nb][1]);

        __syncthreads();
        if (t + 2 < NT) issue((uint32_t)(t & 1) * 20480u, (t + 2) * 32);
    }

    int erow = lane >> 2;
    int ecol = (lane & 3) * 2;
    float* red = (float*)smraw;
    if (wk == 1) {
#pragma unroll
        for (int s = 0; s < 2; s++) {
            int r0 = wm * 32 + s * 16 + erow;
#pragma unroll
            for (int nb = 0; nb < 4; nb++) {
                int col = wn * 32 + nb * 8 + ecol;
                *(float2*)(red + r0 * 68 + col)       = make_float2(acc[s][nb][0], acc[s][nb][1]);
                *(float2*)(red + (r0 + 8) * 68 + col) = make_float2(acc[s][nb][2], acc[s][nb][3]);
            }
        }
    }
    __syncthreads();
    if (wk != 0) return;

#pragma unroll
    for (int s = 0; s < 2; s++) {
        int rl = wm * 32 + s * 16 + erow;
        int r0 = m0 + rl;
#pragma unroll
        for (int nb = 0; nb < 4; nb++) {
            int cl = wn * 32 + nb * 8 + ecol;
            int col = n0 + cl;
            float2 o0 = *(const float2*)(red + rl * 68 + cl);
            float2 o1 = *(const float2*)(red + (rl + 8) * 68 + cl);
            float v00 = acc[s][nb][0] + o0.x, v01 = acc[s][nb][1] + o0.y;
            float v10 = acc[s][nb][2] + o1.x, v11 = acc[s][nb][3] + o1.y;
            if (MODE == 2) {
                *(float2*)(Cf + coff + (long long)r0 * ldc + col)       = make_float2(v00, v01);
                *(float2*)(Cf + coff + (long long)(r0 + 8) * ldc + col) = make_float2(v10, v11);
            } else {
                float b0 = bp ? bp[col] : 0.f;
                float b1 = bp ? bp[col + 1] : 0.f;
                *(float2*)(Cf + coff + (long long)r0 * ldc + col)
                    = make_float2(alpha * (v00 + b0), alpha * (v01 + b1));
                *(float2*)(Cf + coff + (long long)(r0 + 8) * ldc + col)
                    = make_float2(alpha * (v10 + b0), alpha * (v11 + b1));
            }
        }
    }
}

// ---------------------------------------------------------------------------
// Fused attention (R10 version — online softmax, col-sliced xa)
// ---------------------------------------------------------------------------
__global__ __launch_bounds__(256)
void attn_kernel(const float* __restrict__ x,
                 const float* __restrict__ qk,
                 const int*   __restrict__ seg,
                 __nv_bfloat16* __restrict__ xah,
                 __nv_bfloat16* __restrict__ xal)
{
    __shared__ float qks[16 * 260];
    __shared__ float xs [16 * 260];
    __shared__ float sw [16 * 20];
    __shared__ float sscale[16];
    __shared__ float sD[16];

    int b = blockIdx.x;
    int t = threadIdx.x;
    int s0 = seg[b];
    int len = seg[b + 1] - s0;
    if (len > MAXLEN) len = MAXLEN;

    const float4* qk4 = (const float4*)(qk + (long long)b * (NHEAD * D_DRUG));
#pragma unroll
    for (int r = 0; r < 4; r++) {
        int idx = t + r * 256;
        int h = idx >> 6, jj = idx & 63;
        *(float4*)&qks[h * 260 + jj * 4] = qk4[idx];
    }
    __syncthreads();

    int h  = t >> 4;
    int mm = t & 15;
    int w2 = t >> 5, lane = t & 31;
    int hx = lane >> 1, cx = lane & 1;
    int j0x = w2 * 32 + cx * 16;

    float M = -3.0e38f, D = 0.f;
    F2U acc[8];
#pragma unroll
    for (int i = 0; i < 8; i++) acc[i].f = make_float2(0.f, 0.f);

    for (int m0 = 0; m0 < len; m0 += 16) {
        int nm = len - m0; if (nm > 16) nm = 16;
#pragma unroll
        for (int r = 0; r < 4; r++) {
            int idx = t + r * 256;
            int row = idx >> 6, jj = idx & 63;
            if (row < nm)
                *(float4*)&xs[row * 260 + jj * 4] =
                    *(const float4*)(x + (long long)(s0 + m0 + row) * D_DRUG + jj * 4);
        }
        __syncthreads();

        float myscore = -3.0e38f;
        if (mm < nm) {
            const float* qp = &qks[h * 260];
            const float* xp = &xs[mm * 260];
            F2U a0, a1;
            a0.f = make_float2(0.f, 0.f);
            a1.f = make_float2(0.f, 0.f);
#pragma unroll
            for (int j = 0; j < 256; j += 8) {
                float4 q0 = *(const float4*)(qp + j);
                float4 x0 = *(const float4*)(xp + j);
                float4 q1 = *(const float4*)(qp + j + 4);
                float4 x1 = *(const float4*)(xp + j + 4);
                F2U aa, bb;
                aa.f = make_float2(q0.x, q0.y); bb.f = make_float2(x0.x, x0.y); fma2(a0, aa, bb);
                aa.f = make_float2(q0.z, q0.w); bb.f = make_float2(x0.z, x0.w); fma2(a1, aa, bb);
                aa.f = make_float2(q1.x, q1.y); bb.f = make_float2(x1.x, x1.y); fma2(a0, aa, bb);
                aa.f = make_float2(q1.z, q1.w); bb.f = make_float2(x1.z, x1.w); fma2(a1, aa, bb);
            }
            myscore = a0.f.x + a0.f.y + a1.f.x + a1.f.y;
        }

        float tmax = myscore;
#pragma unroll
        for (int o = 1; o < 16; o <<= 1)
            tmax = fmaxf(tmax, __shfl_xor_sync(0xffffffffu, tmax, o));
        float newM = fmaxf(M, tmax);
        float scale = __expf(M - newM);
        float w = (mm < nm) ? __expf(myscore - newM) : 0.f;
        float ws = w;
#pragma unroll
        for (int o = 1; o < 16; o <<= 1)
            ws += __shfl_xor_sync(0xffffffffu, ws, o);
        D = D * scale + ws;
        M = newM;
        sw[h * 20 + mm] = w;
        if (mm == 0) sscale[h] = scale;
        __syncthreads();

        float sc2 = sscale[hx];
#pragma unroll
        for (int i = 0; i < 8; i++) { acc[i].f.x *= sc2; acc[i].f.y *= sc2; }
        const float* swr = &sw[hx * 20];
        for (int i = 0; i < nm; i++) {
            float a = swr[i];
            F2U ad; ad.f = make_float2(a, a);
            const float* xr = &xs[i * 260 + j0x];
#pragma unroll
            for (int r = 0; r < 4; r++) {
                float4 v = *(const float4*)(xr + r * 4);
                F2U b0, b1;
                b0.f = make_float2(v.x, v.y);
                b1.f = make_float2(v.z, v.w);
                fma2(acc[2 * r], ad, b0);
                fma2(acc[2 * r + 1], ad, b1);
            }
        }
        __syncthreads();
    }

    if (mm == 0) sD[h] = D;
    __syncthreads();

    float Df = sD[hx];
    float inv = (Df > 0.f) ? (1.0f / Df) : 0.f;
    long long base = (long long)b * (NHEAD * D_DRUG) + hx * D_DRUG + j0x;
#pragma unroll
    for (int i = 0; i < 8; i++) {
        float va = acc[i].f.x * inv, vb = acc[i].f.y * inv;
        __nv_bfloat16 ha = __float2bfloat16(va), hb = __float2bfloat16(vb);
        uint32_t ph = (uint32_t)__bfloat16_as_ushort(ha)
                    | ((uint32_t)__bfloat16_as_ushort(hb) << 16);
        uint32_t pl = pack_bf16(va - __bfloat162float(ha), vb - __bfloat162float(hb));
        *(uint32_t*)(xah + base + i * 2) = ph;
        *(uint32_t*)(xal + base + i * 2) = pl;
    }
}

// ---------------------------------------------------------------------------
// Launch
// ---------------------------------------------------------------------------
extern "C" void kernel_launch(void* const* d_in, const int* in_sizes, int n_in,
                              void* d_out, int out_size)
{
    const float* x_nodes = (const float*)d_in[0];
    const float* cell    = (const float*)d_in[1];
    const float* Wq      = (const float*)d_in[2];
    const float* bq      = (const float*)d_in[3];
    const float* Wk      = (const float*)d_in[4];
    /* bk cancels in softmax */
    const float* Wv      = (const float*)d_in[6];
    const float* bv      = (const float*)d_in[7];
    const float* Wo      = (const float*)d_in[8];
    const float* bo      = (const float*)d_in[9];
    const float* Wc      = (const float*)d_in[10];
    const float* bc      = (const float*)d_in[11];
    const void*  guide   = d_in[12];
    float*       out     = (float*)d_out;

    int N = in_sizes[12];

    float *qkp, *part; int* seg;
    __nv_bfloat16 *a0h, *a0l, *a1h, *a1l, *xah, *xal;
    __nv_bfloat16 *wch, *wcl, *wqh, *wql, *woh, *wol, *wvh, *wvl, *wkth, *wktl;
    cudaGetSymbolAddress((void**)&qkp,  g_qk);
    cudaGetSymbolAddress((void**)&part, g_part);
    cudaGetSymbolAddress((void**)&seg,  g_seg);
    cudaGetSymbolAddress((void**)&a0h,  g_a0h);
    cudaGetSymbolAddress((void**)&a0l,  g_a0l);
    cudaGetSymbolAddress((void**)&a1h,  g_a1h);
    cudaGetSymbolAddress((void**)&a1l,  g_a1l);
    cudaGetSymbolAddress((void**)&xah,  g_xah);
    cudaGetSymbolAddress((void**)&xal,  g_xal);
    cudaGetSymbolAddress((void**)&wch,  g_wch);
    cudaGetSymbolAddress((void**)&wcl,  g_wcl);
    cudaGetSymbolAddress((void**)&wqh,  g_wqh);
    cudaGetSymbolAddress((void**)&wql,  g_wql);
    cudaGetSymbolAddress((void**)&woh,  g_woh);
    cudaGetSymbolAddress((void**)&wol,  g_wol);
    cudaGetSymbolAddress((void**)&wvh,  g_wvh);
    cudaGetSymbolAddress((void**)&wvl,  g_wvl);
    cudaGetSymbolAddress((void**)&wkth, g_wkth);
    cudaGetSymbolAddress((void**)&wktl, g_wktl);

    const long long PSTR = (long long)BATCH * EMB;

    // 1: prep-A (only G1's inputs)
    prepA_kernel<<<1536, 256>>>((const float4*)Wc, (const float4*)cell,
                                (uint2*)wch, (uint2*)wcl, (uint2*)a0h, (uint2*)a0l);

    // 2: G1 (split-K2, single wave) fused with prep-B
    g1_fused<<<3331, 256>>>(a0h, a0l, wch, wcl, part, PSTR,
                            (const float4*)Wq, (const float4*)Wo, (const float4*)Wv,
                            (const float4*)cell, Wk, guide, N,
                            (uint2*)wqh, (uint2*)wql, (uint2*)woh, (uint2*)wol,
                            (uint2*)wvh, (uint2*)wvl, wkth, wktl, seg, (float4*)out);

    // 3: reduce +bc -> a1 hi/lo (NS=2)
    reduce_k<0, 2><<<512, 256>>>((const float4*)part, bc, nullptr, a1h, a1l, EMB, 1.0f);

    // 4 (profiled slot): G2 q = cq @ Wq^T (split-K2, single wave)
    mma_gemm3x<2><<<dim3(16, 8, 2), 256>>>(
        a1h, a1l, EMB, 0, wqh, wql, EMB, 0, nullptr, 0,
        part, EMB, 0, 1.0f, 512, 2, PSTR);
    // 5: reduce (+bq)*0.125 -> a0 hi/lo
    reduce_k<0, 2><<<512, 256>>>((const float4*)part, bq, nullptr, a0h, a0l, EMB, 0.125f);

    // 6: qk = q @ WkT per head
    mma_gemm3x<1><<<dim3(4, 8, 16), 256>>>(
        a0h, a0l, EMB, HDIM, wkth, wktl, HDIM, (long long)D_DRUG * HDIM, nullptr, 0,
        qkp, NHEAD * D_DRUG, D_DRUG, 1.0f, HDIM, 1, 0);

    // 7: attention
    attn_kernel<<<512, 256>>>(x_nodes, qkp, seg, xah, xal);

    // 8: vv per head (split-K2 -> 256 CTAs, single wave)
    mma_gemm3x<2><<<dim3(1, 8, 32), 256>>>(
        xah, xal, NHEAD * D_DRUG, D_DRUG, wvh, wvl, D_DRUG, (long long)HDIM * D_DRUG,
        nullptr, 0, part, EMB, HDIM, 1.0f, 128, 2, PSTR);
    // 9: reduce +bv -> a1 hi/lo
    reduce_k<0, 2><<<512, 256>>>((const float4*)part, bv, nullptr, a1h, a1l, EMB, 1.0f);

    // 10: G3 out = op @ Wo^T (split-K2)
    mma_gemm3x<2><<<dim3(16, 8, 2), 256>>>(
        a1h, a1l, EMB, 0, woh, wol, EMB, 0, nullptr, 0,
        part, EMB, 0, 1.0f, 512, 2, PSTR);
    // 11: reduce +bo -> fp32 strided into out
    reduce_k<1, 2><<<512, 256>>>((const float4*)part, bo, out, nullptr, nullptr,
                                 EMB + D_CELL, 1.0f);

    (void)n_in; (void)out_size;
}